// round 12
// baseline (speedup 1.0000x reference)
#include <cuda_runtime.h>
#include <cuda_bf16.h>
#include <math.h>

#define BATCH 16
#define CCH   384
#define HN    3136
#define NPAD  3200          // HN padded to multiple of 128
#define TC2   768           // q,k rows only (v eliminated algebraically)
#define KSPL  2             // split-K factor for logits GEMM (3136 = 2*1568)
#define KCH   1568          // K per split part
#define PSTR  ((size_t)BATCH * CCH * CCH)   // partial-buffer stride

// ---------------- scratch (device globals, zero-initialized) ----------------
__device__ __nv_bfloat16 g_xT   [(size_t)BATCH * NPAD * CCH];  // BN(x)^T [b][n][c]
__device__ __nv_bfloat16 g_qkvb [(size_t)BATCH * TC2 * NPAD];  // q,k bf16 [b][2c][n] ld=NPAD
__device__ float         g_attn [KSPL * PSTR];                 // logits partials fp32
__device__ __nv_bfloat16 g_attnb[(size_t)BATCH * CCH * CCH];   // softmax bf16 [c][d]
__device__ __nv_bfloat16 g_w2   [(size_t)BATCH * CCH * CCH];   // W2 = wproj@attn [o][d]
__device__ __nv_bfloat16 g_w3   [(size_t)BATCH * CCH * CCH];   // W3 = W2@Wv [o][c]
__device__ float         g_bias3[BATCH * CCH];                 // b_proj + W2@b_v
__device__ __nv_bfloat16 g_wqkv [3 * CCH * CCH];
__device__ __nv_bfloat16 g_wproj[CCH * CCH];
__device__ float g_sumsq[BATCH * 2 * CCH];                     // per-row sum of squares (q,k)

// ---------------- helpers ----------------
__device__ __forceinline__ unsigned su32(const void* p) {
    return (unsigned)__cvta_generic_to_shared(p);
}
__device__ __forceinline__ unsigned pk(float a, float b) {
    __nv_bfloat162 h = __floats2bfloat162_rn(a, b);
    return *(unsigned*)&h;
}
__device__ __forceinline__ void mma_bf16(float* d, const unsigned* a, unsigned b0, unsigned b1) {
    asm volatile(
        "mma.sync.aligned.m16n8k16.row.col.f32.bf16.bf16.f32 "
        "{%0,%1,%2,%3}, {%4,%5,%6,%7}, {%8,%9}, {%0,%1,%2,%3};\n"
        : "+f"(d[0]), "+f"(d[1]), "+f"(d[2]), "+f"(d[3])
        : "r"(a[0]), "r"(a[1]), "r"(a[2]), "r"(a[3]), "r"(b0), "r"(b1));
}
#define LDSM4(r0,r1,r2,r3,addr) \
    asm volatile("ldmatrix.sync.aligned.m8n8.x4.shared.b16 {%0,%1,%2,%3}, [%4];" \
        : "=r"(r0),"=r"(r1),"=r"(r2),"=r"(r3) : "r"(addr))
#define LDSM4T(r0,r1,r2,r3,addr) \
    asm volatile("ldmatrix.sync.aligned.m8n8.x4.trans.shared.b16 {%0,%1,%2,%3}, [%4];" \
        : "=r"(r0),"=r"(r1),"=r"(r2),"=r"(r3) : "r"(addr))
#define CP16(dst, src) \
    asm volatile("cp.async.cg.shared.global [%0], [%1], 16;" :: "r"(dst), "l"(src))
#define CP_COMMIT() asm volatile("cp.async.commit_group;" ::: "memory")
#define CP_WAIT1()  asm volatile("cp.async.wait_group 1;" ::: "memory")

#define STAGE_BYTES 16384   // A 8KB + B 8KB

// ============================================================
// bf16 GEMM (mma.sync), block 128x128xK32, 3-stage cp.async ring,
// 256 thr = 8 warps (4M x 2N), warp tile 32x64.
// KSP>1: blockIdx.z = zb*KSP + part; C -> partial buffer at part*sPart.
// TRB: B K-major (NT) vs row-major (NN, ldmatrix.trans).
// BIAS with per-batch stride sBias. SQ: fused row sum-of-squares.
// ============================================================
template<int KSP, bool TRB, bool BIAS, bool RES, bool OUTBF, bool GUARDN, bool SQ>
__global__ __launch_bounds__(256, 2)
void bgemm(const __nv_bfloat16* __restrict__ A, const __nv_bfloat16* __restrict__ B,
           void* __restrict__ Cv, const float* __restrict__ bias,
           const float* __restrict__ res,
           int K, int lda, int ldb, int ldc, int nvalid,
           long sA, long sB, long sC, long sR, long sPart, long sBias)
{
    __shared__ __align__(16) unsigned char smem[3 * STAGE_BYTES];
    const unsigned sbase = su32(smem);

    const int tid = threadIdx.x;
    const int wid = tid >> 5, lane = tid & 31;
    const int wm = wid >> 1, wn = wid & 1;
    const int grp = lane >> 2, qd = lane & 3;
    const int row0 = blockIdx.y * 128;
    const int col0 = blockIdx.x * 128;
    int z = blockIdx.z;
    int part = 0;
    if (KSP > 1) { part = z % KSP; z /= KSP; }

    const __nv_bfloat16* Az = A + (size_t)z * sA + (size_t)part * K;
    const __nv_bfloat16* Bz = B + (size_t)z * sB + (size_t)part * K;
    const __nv_bfloat16* Ab = Az + (size_t)row0 * lda;
    const __nv_bfloat16* Bb = TRB ? (Bz + (size_t)col0 * ldb) : (Bz + col0);

    // ---- A loader geometry (rows of 64B, 4 chunks) ----
    const int lr = tid >> 2, lc = tid & 3;
    const unsigned aoff1 = (unsigned)(lr * 64 + ((lc ^ ((lr >> 1) & 3)) * 16));
    const int lr2 = lr + 64;
    const unsigned aoff2 = (unsigned)(lr2 * 64 + ((lc ^ ((lr2 >> 1) & 3)) * 16));

    // ---- NN B loader geometry (32 k-rows x 16 chunks -> 2 halves) ----
    const int nk1 = tid >> 4, nc1 = tid & 15;
    const unsigned nboff1 = (unsigned)((nc1 >> 3) * 4096 + nk1 * 128 + (((nc1 & 7) ^ (nk1 & 7)) * 16));
    const int nk2 = (tid + 256) >> 4, nc2 = tid & 15;
    const unsigned nboff2 = (unsigned)((nc2 >> 3) * 4096 + nk2 * 128 + (((nc2 & 7) ^ (nk2 & 7)) * 16));

    const int T = K >> 5;

    // ---- fragment geometry ----
    int arow_l[2];
    #pragma unroll
    for (int mi = 0; mi < 2; mi++) arow_l[mi] = wm * 32 + mi * 16 + (lane & 15);
    const int achk = lane >> 4;
    const int bn_base = wn * 64 + ((lane >> 4) << 3) + (lane & 7);
    const int boct = (lane >> 3) & 1;
    const int nn_kl = lane & 15;
    const int nn_ch = lane >> 4;

    float acc[2][8][4] = {};

    auto issue = [&](int s, int k0) {
        const unsigned sa = sbase + s * STAGE_BYTES;
        const unsigned sb = sa + 8192;
        CP16(sa + aoff1, Ab + (size_t)lr  * lda + k0 + lc * 8);
        CP16(sa + aoff2, Ab + (size_t)lr2 * lda + k0 + lc * 8);
        if (TRB) {
            CP16(sb + aoff1, Bb + (size_t)lr  * ldb + k0 + lc * 8);
            CP16(sb + aoff2, Bb + (size_t)lr2 * ldb + k0 + lc * 8);
        } else {
            CP16(sb + nboff1, Bb + (size_t)(k0 + nk1) * ldb + nc1 * 8);
            CP16(sb + nboff2, Bb + (size_t)(k0 + nk2) * ldb + nc2 * 8);
        }
        CP_COMMIT();
    };

    issue(0, 0);
    issue(1, 32);

    for (int t = 0; t < T; t++) {
        CP_WAIT1();
        __syncthreads();

        if (t + 2 < T) issue((t + 2) % 3, (t + 2) << 5);
        else CP_COMMIT();

        const unsigned sa = sbase + (t % 3) * STAGE_BYTES;
        const unsigned sb = sa + 8192;

        #pragma unroll
        for (int ks = 0; ks < 2; ks++) {
            unsigned af[2][4];
            #pragma unroll
            for (int mi = 0; mi < 2; mi++) {
                unsigned addr = sa + arow_l[mi] * 64 +
                    (((ks * 2 + achk) ^ ((arow_l[mi] >> 1) & 3)) * 16);
                LDSM4(af[mi][0], af[mi][1], af[mi][2], af[mi][3], addr);
            }
            unsigned bq[4][4];
            if (TRB) {
                #pragma unroll
                for (int nj = 0; nj < 4; nj++) {
                    int nl = bn_base + nj * 16;
                    unsigned addr = sb + nl * 64 +
                        (((ks * 2 + boct) ^ ((nl >> 1) & 3)) * 16);
                    LDSM4(bq[nj][0], bq[nj][1], bq[nj][2], bq[nj][3], addr);
                }
            } else {
                const int kl = ks * 16 + nn_kl;
                const unsigned sbh = sb + wn * 4096 + kl * 128;
                #pragma unroll
                for (int nj = 0; nj < 4; nj++) {
                    unsigned addr = sbh + (((nj * 2 + nn_ch) ^ (kl & 7)) * 16);
                    LDSM4T(bq[nj][0], bq[nj][1], bq[nj][2], bq[nj][3], addr);
                }
            }
            #pragma unroll
            for (int nj = 0; nj < 4; nj++) {
                #pragma unroll
                for (int p = 0; p < 2; p++) {
                    unsigned b0 = bq[nj][p * 2], b1 = bq[nj][p * 2 + 1];
                    const int ni = nj * 2 + p;
                    #pragma unroll
                    for (int mi = 0; mi < 2; mi++)
                        mma_bf16(acc[mi][ni], af[mi], b0, b1);
                }
            }
        }
    }

    // ---- epilogue ----
    const bool sq_blk = SQ && (row0 < 2 * CCH);
    #pragma unroll
    for (int mi = 0; mi < 2; mi++) {
        const int r0 = row0 + wm * 32 + mi * 16 + grp;
        const int r1 = r0 + 8;
        float bv0 = 0.0f, bv1 = 0.0f;
        if (BIAS) {
            const float* bp = bias + (size_t)z * sBias;
            bv0 = bp[r0]; bv1 = bp[r1];
        }
        float s0 = 0.0f, s1 = 0.0f;
        #pragma unroll
        for (int ni = 0; ni < 8; ni++) {
            const int c = col0 + wn * 64 + ni * 8 + 2 * qd;
            if (GUARDN && c >= nvalid) continue;
            float d0 = acc[mi][ni][0] + bv0, d1 = acc[mi][ni][1] + bv0;
            float d2 = acc[mi][ni][2] + bv1, d3 = acc[mi][ni][3] + bv1;
            if (RES) {
                const float* rp = res + (size_t)z * sR;
                float2 q0 = *(const float2*)&rp[(size_t)r0 * ldc + c];
                float2 q1 = *(const float2*)&rp[(size_t)r1 * ldc + c];
                d0 += q0.x; d1 += q0.y; d2 += q1.x; d3 += q1.y;
            }
            if (SQ) {
                if (sq_blk && c < nvalid) {
                    s0 += d0 * d0 + d1 * d1;
                    s1 += d2 * d2 + d3 * d3;
                }
            }
            if (OUTBF) {
                __nv_bfloat16* Cb = (__nv_bfloat16*)Cv + (size_t)z * sC;
                *(unsigned*)&Cb[(size_t)r0 * ldc + c] = pk(d0, d1);
                *(unsigned*)&Cb[(size_t)r1 * ldc + c] = pk(d2, d3);
            } else {
                float* Cf = (float*)Cv + (size_t)z * sC + (size_t)part * sPart;
                *(float2*)&Cf[(size_t)r0 * ldc + c] = make_float2(d0, d1);
                *(float2*)&Cf[(size_t)r1 * ldc + c] = make_float2(d2, d3);
            }
        }
        if (SQ && sq_blk) {
            s0 += __shfl_xor_sync(0xffffffffu, s0, 1);
            s0 += __shfl_xor_sync(0xffffffffu, s0, 2);
            s1 += __shfl_xor_sync(0xffffffffu, s1, 1);
            s1 += __shfl_xor_sync(0xffffffffu, s1, 2);
            if (qd == 0) {
                atomicAdd(&g_sumsq[(size_t)z * 2 * CCH + r0], s0);
                atomicAdd(&g_sumsq[(size_t)z * 2 * CCH + r1], s1);
            }
        }
    }
}

// ---------------- prep / elementwise ----------------
// both weights -> bf16 in one launch (all 3C rows of wqkv kept: v-part feeds W3)
__global__ void f2b2(const float* __restrict__ s1, int n1,
                     const float* __restrict__ s2, int n2) {
    int i = blockIdx.x * 256 + threadIdx.x;
    if (i < n1) g_wqkv[i] = __float2bfloat16(s1[i]);
    else if (i < n1 + n2) g_wproj[i - n1] = __float2bfloat16(s2[i - n1]);
}

// x [b][c][3136] fp32 --BN (inline fold)--> xT [b][n][384] bf16. 64x64 tiles.
__global__ __launch_bounds__(256)
void prep_xT(const float* __restrict__ x,
             const float* __restrict__ gamma, const float* __restrict__ beta,
             const float* __restrict__ mean,  const float* __restrict__ var) {
    __shared__ float tl[64][65];
    const int b = blockIdx.z;
    const int n0 = blockIdx.x * 64, c0 = blockIdx.y * 64;
    const int tid = threadIdx.x;
    const float* xb = x + (size_t)b * CCH * HN;

    {
        const int cl = tid >> 2;
        const int c = c0 + cl;
        const float s = gamma[c] * rsqrtf(var[c] + 1e-5f);
        const float h = beta[c] - mean[c] * s;
        const float* src = xb + (size_t)c * HN + n0;
        #pragma unroll
        for (int j = 0; j < 4; j++) {
            int f = (tid & 3) + j * 4;
            float4 v = *(const float4*)(src + f * 4);
            tl[cl][f * 4 + 0] = v.x * s + h;
            tl[cl][f * 4 + 1] = v.y * s + h;
            tl[cl][f * 4 + 2] = v.z * s + h;
            tl[cl][f * 4 + 3] = v.w * s + h;
        }
    }
    __syncthreads();

    {
        const int nl = tid >> 2;
        __nv_bfloat16* dst = g_xT + (size_t)b * NPAD * CCH + (size_t)(n0 + nl) * CCH + c0;
        #pragma unroll
        for (int j = 0; j < 2; j++) {
            int u = (tid & 3) + j * 4;
            int cc = u * 8;
            uint4 o;
            o.x = pk(tl[cc + 0][nl], tl[cc + 1][nl]);
            o.y = pk(tl[cc + 2][nl], tl[cc + 3][nl]);
            o.z = pk(tl[cc + 4][nl], tl[cc + 5][nl]);
            o.w = pk(tl[cc + 6][nl], tl[cc + 7][nl]);
            *(uint4*)(dst + cc) = o;
        }
    }
}

// softmax over last dim (384): sums KSPL partials, applies t*invq[c]*invk[d]
__global__ __launch_bounds__(128)
void softmax_rows(const float* __restrict__ tptr) {
    const int b = blockIdx.y, cc = blockIdx.x;
    const size_t ridx = (size_t)b * CCH + cc;
    const float* row = g_attn + ridx * CCH;
    __nv_bfloat16* orow = g_attnb + ridx * CCH;
    const int tid = threadIdx.x;
    __shared__ float red[128];

    const float* ssq = g_sumsq + (size_t)b * 2 * CCH;
    const float tq = tptr[0] / fmaxf(sqrtf(ssq[cc]), 1e-12f);
    const float* sk = ssq + CCH;
    const float ik0 = 1.0f / fmaxf(sqrtf(sk[tid]),       1e-12f);
    const float ik1 = 1.0f / fmaxf(sqrtf(sk[tid + 128]), 1e-12f);
    const float ik2 = 1.0f / fmaxf(sqrtf(sk[tid + 256]), 1e-12f);

    float v0 = 0.0f, v1 = 0.0f, v2 = 0.0f;
    #pragma unroll
    for (int p = 0; p < KSPL; p++) {
        const float* rp = row + (size_t)p * PSTR;
        v0 += rp[tid];
        v1 += rp[tid + 128];
        v2 += rp[tid + 256];
    }
    v0 *= tq * ik0;
    v1 *= tq * ik1;
    v2 *= tq * ik2;

    float m = fmaxf(v0, fmaxf(v1, v2));
    red[tid] = m;
    __syncthreads();
    for (int s = 64; s > 0; s >>= 1) {
        if (tid < s) red[tid] = fmaxf(red[tid], red[tid + s]);
        __syncthreads();
    }
    m = red[0];
    __syncthreads();

    float e0 = expf(v0 - m), e1 = expf(v1 - m), e2 = expf(v2 - m);
    red[tid] = e0 + e1 + e2;
    __syncthreads();
    for (int s = 64; s > 0; s >>= 1) {
        if (tid < s) red[tid] += red[tid + s];
        __syncthreads();
    }
    float inv = 1.0f / red[0];

    orow[tid]       = __float2bfloat16(e0 * inv);
    orow[tid + 128] = __float2bfloat16(e1 * inv);
    orow[tid + 256] = __float2bfloat16(e2 * inv);
}

// bias3[b][o] = b_proj[o] + sum_d W2[b][o][d] * b_qkv[2C + d]
__global__ __launch_bounds__(256)
void bias3_kernel(const float* __restrict__ b_proj, const float* __restrict__ b_qkv) {
    int i = blockIdx.x * 256 + threadIdx.x;   // i = b*CCH + o
    if (i >= BATCH * CCH) return;
    const __nv_bfloat16* w2row = g_w2 + (size_t)i * CCH;
    const float* bv = b_qkv + 2 * CCH;
    float s = 0.0f;
    for (int d = 0; d < CCH; d++)
        s += __bfloat162float(w2row[d]) * bv[d];
    g_bias3[i] = b_proj[i % CCH] + s;
}

// ---------------- host ----------------
extern "C" void kernel_launch(void* const* d_in, const int* in_sizes, int n_in,
                              void* d_out, int out_size)
{
    const float* x      = (const float*)d_in[0];
    const float* w_qkv  = (const float*)d_in[1];
    const float* b_qkv  = (const float*)d_in[2];
    const float* w_proj = (const float*)d_in[3];
    const float* b_proj = (const float*)d_in[4];
    const float* gamma  = (const float*)d_in[5];
    const float* beta   = (const float*)d_in[6];
    const float* mean   = (const float*)d_in[7];
    const float* var    = (const float*)d_in[8];
    const float* temp   = (const float*)d_in[9];
    float* out = (float*)d_out;

    __nv_bfloat16 *qkvb, *attnb, *w2, *w3, *wqkvb, *wprojb, *xT;
    float *attn, *sumsq, *bias3;
    cudaGetSymbolAddress((void**)&xT,     g_xT);
    cudaGetSymbolAddress((void**)&qkvb,   g_qkvb);
    cudaGetSymbolAddress((void**)&attn,   g_attn);
    cudaGetSymbolAddress((void**)&attnb,  g_attnb);
    cudaGetSymbolAddress((void**)&w2,     g_w2);
    cudaGetSymbolAddress((void**)&w3,     g_w3);
    cudaGetSymbolAddress((void**)&wqkvb,  g_wqkv);
    cudaGetSymbolAddress((void**)&wprojb, g_wproj);
    cudaGetSymbolAddress((void**)&sumsq,  g_sumsq);
    cudaGetSymbolAddress((void**)&bias3,  g_bias3);

    const long sQKV = (long)TC2 * NPAD;
    const long sNC  = (long)NPAD * CCH;
    const long sATT = (long)CCH * CCH;
    const long sOUT = (long)CCH * HN;

    // 0) prep
    cudaMemsetAsync(sumsq, 0, (size_t)BATCH * 2 * CCH * sizeof(float));
    f2b2<<<(3*CCH*CCH + CCH*CCH + 255)/256, 256>>>(w_qkv, 3*CCH*CCH, w_proj, CCH*CCH);
    prep_xT<<<dim3(HN/64, CCH/64, BATCH), 256>>>(x, gamma, beta, mean, var);

    // 1) q,k = wqkv[0:768] . xT^T + b_qkv (NT, M=768) + fused sum-of-squares
    bgemm<1, true, true, false, true, false, true>
        <<<dim3(NPAD/128, TC2/128, BATCH), 256>>>(
        wqkvb, xT, qkvb, b_qkv, nullptr,
        CCH, CCH, CCH, NPAD, HN, 0, sNC, sQKV, 0, 0, 0);

    // 2) logits partials: split-K=2 (NT, fp32 partials)
    bgemm<KSPL, true, false, false, false, false, false>
        <<<dim3(CCH/128, CCH/128, BATCH*KSPL), 256>>>(
        qkvb, qkvb + (size_t)CCH*NPAD, attn, nullptr, nullptr,
        KCH, NPAD, NPAD, CCH, CCH, sQKV, sQKV, sATT, 0, (long)PSTR, 0);

    // 3) softmax (sums partials, inline inverse norms, temperature) -> bf16
    softmax_rows<<<dim3(CCH, BATCH), 128>>>(temp);

    // 4) W2[o,d] = wproj[o,:] . attn[:,d]   (NN, 384^3), bf16
    bgemm<1, false, false, false, true, false, false>
        <<<dim3(CCH/128, CCH/128, BATCH), 256>>>(
        wprojb, attnb, w2, nullptr, nullptr,
        CCH, CCH, CCH, CCH, CCH, 0, sATT, sATT, 0, 0, 0);

    // 5) W3[o,c] = W2[o,:] . Wv[:,c]   (NN, 384^3; Wv = wqkv rows [2C,3C)), bf16
    bgemm<1, false, false, false, true, false, false>
        <<<dim3(CCH/128, CCH/128, BATCH), 256>>>(
        w2, wqkvb + (size_t)2*CCH*CCH, w3, nullptr, nullptr,
        CCH, CCH, CCH, CCH, CCH, sATT, 0, sATT, 0, 0, 0);

    // 5b) bias3 = b_proj + W2 @ b_v
    bias3_kernel<<<(BATCH*CCH + 255)/256, 256>>>(b_proj, b_qkv);

    // 6) out[o,n] = W3[o,:] . xT[n,:] + bias3 + x   (NT, fp32, guarded)
    bgemm<1, true, true, true, false, true, false>
        <<<dim3(NPAD/128, CCH/128, BATCH), 256>>>(
        w3, xT, out, bias3, x,
        CCH, CCH, CCH, HN, HN, sATT, sNC, sOUT, sOUT, 0, CCH);
}

// round 13
// speedup vs baseline: 1.1808x; 1.1808x over previous
#include <cuda_runtime.h>
#include <cuda_bf16.h>
#include <math.h>

#define BATCH 16
#define CCH   384
#define HN    3136
#define NPAD  3200          // HN padded to multiple of 128
#define TC2   768           // q,k rows only (v eliminated algebraically)
#define KSPL  2             // split-K factor for logits GEMM (3136 = 2*1568)
#define KCH   1568          // K per split part
#define PSTR  ((size_t)BATCH * CCH * CCH)   // partial-buffer stride

// ---------------- scratch (device globals, zero-initialized) ----------------
__device__ __nv_bfloat16 g_xT   [(size_t)BATCH * NPAD * CCH];  // BN(x)^T [b][n][c]
__device__ __nv_bfloat16 g_qkvb [(size_t)BATCH * TC2 * NPAD];  // q,k bf16 [b][2c][n] ld=NPAD
__device__ float         g_attn [KSPL * PSTR];                 // logits partials fp32
__device__ __nv_bfloat16 g_attnb[(size_t)BATCH * CCH * CCH];   // softmax bf16 [c][d]
__device__ __nv_bfloat16 g_w2   [(size_t)BATCH * CCH * CCH];   // W2 = wproj@attn [o][d]
__device__ __nv_bfloat16 g_w3   [(size_t)BATCH * CCH * CCH];   // W3 = W2@Wv [o][c]
__device__ float         g_bias3[BATCH * CCH];                 // b_proj + W2@b_v
__device__ __nv_bfloat16 g_wqkv [3 * CCH * CCH];
__device__ __nv_bfloat16 g_wproj[CCH * CCH];
__device__ float g_sumsq[BATCH * 2 * CCH];                     // per-row sum of squares (q,k)

// ---------------- helpers ----------------
__device__ __forceinline__ unsigned su32(const void* p) {
    return (unsigned)__cvta_generic_to_shared(p);
}
__device__ __forceinline__ unsigned pk(float a, float b) {
    __nv_bfloat162 h = __floats2bfloat162_rn(a, b);
    return *(unsigned*)&h;
}
__device__ __forceinline__ void mma_bf16(float* d, const unsigned* a, unsigned b0, unsigned b1) {
    asm volatile(
        "mma.sync.aligned.m16n8k16.row.col.f32.bf16.bf16.f32 "
        "{%0,%1,%2,%3}, {%4,%5,%6,%7}, {%8,%9}, {%0,%1,%2,%3};\n"
        : "+f"(d[0]), "+f"(d[1]), "+f"(d[2]), "+f"(d[3])
        : "r"(a[0]), "r"(a[1]), "r"(a[2]), "r"(a[3]), "r"(b0), "r"(b1));
}
#define LDSM4(r0,r1,r2,r3,addr) \
    asm volatile("ldmatrix.sync.aligned.m8n8.x4.shared.b16 {%0,%1,%2,%3}, [%4];" \
        : "=r"(r0),"=r"(r1),"=r"(r2),"=r"(r3) : "r"(addr))
#define LDSM4T(r0,r1,r2,r3,addr) \
    asm volatile("ldmatrix.sync.aligned.m8n8.x4.trans.shared.b16 {%0,%1,%2,%3}, [%4];" \
        : "=r"(r0),"=r"(r1),"=r"(r2),"=r"(r3) : "r"(addr))
#define CP16(dst, src) \
    asm volatile("cp.async.cg.shared.global [%0], [%1], 16;" :: "r"(dst), "l"(src))
#define CP_COMMIT() asm volatile("cp.async.commit_group;" ::: "memory")
#define CP_WAIT1()  asm volatile("cp.async.wait_group 1;" ::: "memory")

#define STAGE_BYTES 16384   // A 8KB + B 8KB

// ============================================================
// bf16 GEMM (mma.sync), block 128x128xK32, 3-stage cp.async ring,
// 256 thr = 8 warps (4M x 2N), warp tile 32x64.
// ============================================================
template<int KSP, bool TRB, bool BIAS, bool RES, bool OUTBF, bool GUARDN, bool SQ>
__global__ __launch_bounds__(256, 2)
void bgemm(const __nv_bfloat16* __restrict__ A, const __nv_bfloat16* __restrict__ B,
           void* __restrict__ Cv, const float* __restrict__ bias,
           const float* __restrict__ res,
           int K, int lda, int ldb, int ldc, int nvalid,
           long sA, long sB, long sC, long sR, long sPart, long sBias)
{
    __shared__ __align__(16) unsigned char smem[3 * STAGE_BYTES];
    const unsigned sbase = su32(smem);

    const int tid = threadIdx.x;
    const int wid = tid >> 5, lane = tid & 31;
    const int wm = wid >> 1, wn = wid & 1;
    const int grp = lane >> 2, qd = lane & 3;
    const int row0 = blockIdx.y * 128;
    const int col0 = blockIdx.x * 128;
    int z = blockIdx.z;
    int part = 0;
    if (KSP > 1) { part = z % KSP; z /= KSP; }

    const __nv_bfloat16* Az = A + (size_t)z * sA + (size_t)part * K;
    const __nv_bfloat16* Bz = B + (size_t)z * sB + (size_t)part * K;
    const __nv_bfloat16* Ab = Az + (size_t)row0 * lda;
    const __nv_bfloat16* Bb = TRB ? (Bz + (size_t)col0 * ldb) : (Bz + col0);

    // ---- A loader geometry ----
    const int lr = tid >> 2, lc = tid & 3;
    const unsigned aoff1 = (unsigned)(lr * 64 + ((lc ^ ((lr >> 1) & 3)) * 16));
    const int lr2 = lr + 64;
    const unsigned aoff2 = (unsigned)(lr2 * 64 + ((lc ^ ((lr2 >> 1) & 3)) * 16));

    // ---- NN B loader geometry ----
    const int nk1 = tid >> 4, nc1 = tid & 15;
    const unsigned nboff1 = (unsigned)((nc1 >> 3) * 4096 + nk1 * 128 + (((nc1 & 7) ^ (nk1 & 7)) * 16));
    const int nk2 = (tid + 256) >> 4, nc2 = tid & 15;
    const unsigned nboff2 = (unsigned)((nc2 >> 3) * 4096 + nk2 * 128 + (((nc2 & 7) ^ (nk2 & 7)) * 16));

    const int T = K >> 5;

    // ---- fragment geometry ----
    int arow_l[2];
    #pragma unroll
    for (int mi = 0; mi < 2; mi++) arow_l[mi] = wm * 32 + mi * 16 + (lane & 15);
    const int achk = lane >> 4;
    const int bn_base = wn * 64 + ((lane >> 4) << 3) + (lane & 7);
    const int boct = (lane >> 3) & 1;
    const int nn_kl = lane & 15;
    const int nn_ch = lane >> 4;

    float acc[2][8][4] = {};

    auto issue = [&](int s, int k0) {
        const unsigned sa = sbase + s * STAGE_BYTES;
        const unsigned sb = sa + 8192;
        CP16(sa + aoff1, Ab + (size_t)lr  * lda + k0 + lc * 8);
        CP16(sa + aoff2, Ab + (size_t)lr2 * lda + k0 + lc * 8);
        if (TRB) {
            CP16(sb + aoff1, Bb + (size_t)lr  * ldb + k0 + lc * 8);
            CP16(sb + aoff2, Bb + (size_t)lr2 * ldb + k0 + lc * 8);
        } else {
            CP16(sb + nboff1, Bb + (size_t)(k0 + nk1) * ldb + nc1 * 8);
            CP16(sb + nboff2, Bb + (size_t)(k0 + nk2) * ldb + nc2 * 8);
        }
        CP_COMMIT();
    };

    issue(0, 0);
    issue(1, 32);

    for (int t = 0; t < T; t++) {
        CP_WAIT1();
        __syncthreads();

        if (t + 2 < T) issue((t + 2) % 3, (t + 2) << 5);
        else CP_COMMIT();

        const unsigned sa = sbase + (t % 3) * STAGE_BYTES;
        const unsigned sb = sa + 8192;

        #pragma unroll
        for (int ks = 0; ks < 2; ks++) {
            unsigned af[2][4];
            #pragma unroll
            for (int mi = 0; mi < 2; mi++) {
                unsigned addr = sa + arow_l[mi] * 64 +
                    (((ks * 2 + achk) ^ ((arow_l[mi] >> 1) & 3)) * 16);
                LDSM4(af[mi][0], af[mi][1], af[mi][2], af[mi][3], addr);
            }
            unsigned bq[4][4];
            if (TRB) {
                #pragma unroll
                for (int nj = 0; nj < 4; nj++) {
                    int nl = bn_base + nj * 16;
                    unsigned addr = sb + nl * 64 +
                        (((ks * 2 + boct) ^ ((nl >> 1) & 3)) * 16);
                    LDSM4(bq[nj][0], bq[nj][1], bq[nj][2], bq[nj][3], addr);
                }
            } else {
                const int kl = ks * 16 + nn_kl;
                const unsigned sbh = sb + wn * 4096 + kl * 128;
                #pragma unroll
                for (int nj = 0; nj < 4; nj++) {
                    unsigned addr = sbh + (((nj * 2 + nn_ch) ^ (kl & 7)) * 16);
                    LDSM4T(bq[nj][0], bq[nj][1], bq[nj][2], bq[nj][3], addr);
                }
            }
            #pragma unroll
            for (int nj = 0; nj < 4; nj++) {
                #pragma unroll
                for (int p = 0; p < 2; p++) {
                    unsigned b0 = bq[nj][p * 2], b1 = bq[nj][p * 2 + 1];
                    const int ni = nj * 2 + p;
                    #pragma unroll
                    for (int mi = 0; mi < 2; mi++)
                        mma_bf16(acc[mi][ni], af[mi], b0, b1);
                }
            }
        }
    }

    // ---- epilogue ----
    const bool sq_blk = SQ && (row0 < 2 * CCH);
    #pragma unroll
    for (int mi = 0; mi < 2; mi++) {
        const int r0 = row0 + wm * 32 + mi * 16 + grp;
        const int r1 = r0 + 8;
        float bv0 = 0.0f, bv1 = 0.0f;
        if (BIAS) {
            const float* bp = bias + (size_t)z * sBias;
            bv0 = bp[r0]; bv1 = bp[r1];
        }
        float s0 = 0.0f, s1 = 0.0f;
        #pragma unroll
        for (int ni = 0; ni < 8; ni++) {
            const int c = col0 + wn * 64 + ni * 8 + 2 * qd;
            if (GUARDN && c >= nvalid) continue;
            float d0 = acc[mi][ni][0] + bv0, d1 = acc[mi][ni][1] + bv0;
            float d2 = acc[mi][ni][2] + bv1, d3 = acc[mi][ni][3] + bv1;
            if (RES) {
                const float* rp = res + (size_t)z * sR;
                float2 q0 = *(const float2*)&rp[(size_t)r0 * ldc + c];
                float2 q1 = *(const float2*)&rp[(size_t)r1 * ldc + c];
                d0 += q0.x; d1 += q0.y; d2 += q1.x; d3 += q1.y;
            }
            if (SQ) {
                if (sq_blk && c < nvalid) {
                    s0 += d0 * d0 + d1 * d1;
                    s1 += d2 * d2 + d3 * d3;
                }
            }
            if (OUTBF) {
                __nv_bfloat16* Cb = (__nv_bfloat16*)Cv + (size_t)z * sC;
                *(unsigned*)&Cb[(size_t)r0 * ldc + c] = pk(d0, d1);
                *(unsigned*)&Cb[(size_t)r1 * ldc + c] = pk(d2, d3);
            } else {
                float* Cf = (float*)Cv + (size_t)z * sC + (size_t)part * sPart;
                *(float2*)&Cf[(size_t)r0 * ldc + c] = make_float2(d0, d1);
                *(float2*)&Cf[(size_t)r1 * ldc + c] = make_float2(d2, d3);
            }
        }
        if (SQ && sq_blk) {
            s0 += __shfl_xor_sync(0xffffffffu, s0, 1);
            s0 += __shfl_xor_sync(0xffffffffu, s0, 2);
            s1 += __shfl_xor_sync(0xffffffffu, s1, 1);
            s1 += __shfl_xor_sync(0xffffffffu, s1, 2);
            if (qd == 0) {
                atomicAdd(&g_sumsq[(size_t)z * 2 * CCH + r0], s0);
                atomicAdd(&g_sumsq[(size_t)z * 2 * CCH + r1], s1);
            }
        }
    }
}

// ---------------- prep / elementwise ----------------
__global__ void f2b2(const float* __restrict__ s1, int n1,
                     const float* __restrict__ s2, int n2) {
    int i = blockIdx.x * 256 + threadIdx.x;
    if (i < n1) g_wqkv[i] = __float2bfloat16(s1[i]);
    else if (i < n1 + n2) g_wproj[i - n1] = __float2bfloat16(s2[i - n1]);
}

// x [b][c][3136] fp32 --BN (inline fold)--> xT [b][n][384] bf16. 64x64 tiles.
__global__ __launch_bounds__(256)
void prep_xT(const float* __restrict__ x,
             const float* __restrict__ gamma, const float* __restrict__ beta,
             const float* __restrict__ mean,  const float* __restrict__ var) {
    __shared__ float tl[64][65];
    const int b = blockIdx.z;
    const int n0 = blockIdx.x * 64, c0 = blockIdx.y * 64;
    const int tid = threadIdx.x;
    const float* xb = x + (size_t)b * CCH * HN;

    {
        const int cl = tid >> 2;
        const int c = c0 + cl;
        const float s = gamma[c] * rsqrtf(var[c] + 1e-5f);
        const float h = beta[c] - mean[c] * s;
        const float* src = xb + (size_t)c * HN + n0;
        #pragma unroll
        for (int j = 0; j < 4; j++) {
            int f = (tid & 3) + j * 4;
            float4 v = *(const float4*)(src + f * 4);
            tl[cl][f * 4 + 0] = v.x * s + h;
            tl[cl][f * 4 + 1] = v.y * s + h;
            tl[cl][f * 4 + 2] = v.z * s + h;
            tl[cl][f * 4 + 3] = v.w * s + h;
        }
    }
    __syncthreads();

    {
        const int nl = tid >> 2;
        __nv_bfloat16* dst = g_xT + (size_t)b * NPAD * CCH + (size_t)(n0 + nl) * CCH + c0;
        #pragma unroll
        for (int j = 0; j < 2; j++) {
            int u = (tid & 3) + j * 4;
            int cc = u * 8;
            uint4 o;
            o.x = pk(tl[cc + 0][nl], tl[cc + 1][nl]);
            o.y = pk(tl[cc + 2][nl], tl[cc + 3][nl]);
            o.z = pk(tl[cc + 4][nl], tl[cc + 5][nl]);
            o.w = pk(tl[cc + 6][nl], tl[cc + 7][nl]);
            *(uint4*)(dst + cc) = o;
        }
    }
}

// softmax over last dim (384): sums KSPL partials, applies t*invq[c]*invk[d]
__global__ __launch_bounds__(128)
void softmax_rows(const float* __restrict__ tptr) {
    const int b = blockIdx.y, cc = blockIdx.x;
    const size_t ridx = (size_t)b * CCH + cc;
    const float* row = g_attn + ridx * CCH;
    __nv_bfloat16* orow = g_attnb + ridx * CCH;
    const int tid = threadIdx.x;
    __shared__ float red[128];

    const float* ssq = g_sumsq + (size_t)b * 2 * CCH;
    const float tq = tptr[0] / fmaxf(sqrtf(ssq[cc]), 1e-12f);
    const float* sk = ssq + CCH;
    const float ik0 = 1.0f / fmaxf(sqrtf(sk[tid]),       1e-12f);
    const float ik1 = 1.0f / fmaxf(sqrtf(sk[tid + 128]), 1e-12f);
    const float ik2 = 1.0f / fmaxf(sqrtf(sk[tid + 256]), 1e-12f);

    float v0 = 0.0f, v1 = 0.0f, v2 = 0.0f;
    #pragma unroll
    for (int p = 0; p < KSPL; p++) {
        const float* rp = row + (size_t)p * PSTR;
        v0 += rp[tid];
        v1 += rp[tid + 128];
        v2 += rp[tid + 256];
    }
    v0 *= tq * ik0;
    v1 *= tq * ik1;
    v2 *= tq * ik2;

    float m = fmaxf(v0, fmaxf(v1, v2));
    red[tid] = m;
    __syncthreads();
    for (int s = 64; s > 0; s >>= 1) {
        if (tid < s) red[tid] = fmaxf(red[tid], red[tid + s]);
        __syncthreads();
    }
    m = red[0];
    __syncthreads();

    float e0 = expf(v0 - m), e1 = expf(v1 - m), e2 = expf(v2 - m);
    red[tid] = e0 + e1 + e2;
    __syncthreads();
    for (int s = 64; s > 0; s >>= 1) {
        if (tid < s) red[tid] += red[tid + s];
        __syncthreads();
    }
    float inv = 1.0f / red[0];

    orow[tid]       = __float2bfloat16(e0 * inv);
    orow[tid + 128] = __float2bfloat16(e1 * inv);
    orow[tid + 256] = __float2bfloat16(e2 * inv);
}

// bias3[b][o] = b_proj[o] + sum_d W2[b][o][d] * b_qkv[2C+d]
// block per (b,o) row, 128 threads, coalesced bf16 loads + tree reduce.
__global__ __launch_bounds__(128)
void bias3_kernel(const float* __restrict__ b_proj, const float* __restrict__ b_qkv) {
    const int row = blockIdx.x;                  // b*CCH + o
    const __nv_bfloat16* w2row = g_w2 + (size_t)row * CCH;
    const float* bv = b_qkv + 2 * CCH;
    const int tid = threadIdx.x;
    __shared__ float red[128];

    float s = __bfloat162float(w2row[tid])       * bv[tid]
            + __bfloat162float(w2row[tid + 128]) * bv[tid + 128]
            + __bfloat162float(w2row[tid + 256]) * bv[tid + 256];
    red[tid] = s;
    __syncthreads();
    for (int st = 64; st > 0; st >>= 1) {
        if (tid < st) red[tid] += red[tid + st];
        __syncthreads();
    }
    if (tid == 0)
        g_bias3[row] = b_proj[row % CCH] + red[0];
}

// ---------------- host ----------------
extern "C" void kernel_launch(void* const* d_in, const int* in_sizes, int n_in,
                              void* d_out, int out_size)
{
    const float* x      = (const float*)d_in[0];
    const float* w_qkv  = (const float*)d_in[1];
    const float* b_qkv  = (const float*)d_in[2];
    const float* w_proj = (const float*)d_in[3];
    const float* b_proj = (const float*)d_in[4];
    const float* gamma  = (const float*)d_in[5];
    const float* beta   = (const float*)d_in[6];
    const float* mean   = (const float*)d_in[7];
    const float* var    = (const float*)d_in[8];
    const float* temp   = (const float*)d_in[9];
    float* out = (float*)d_out;

    __nv_bfloat16 *qkvb, *attnb, *w2, *w3, *wqkvb, *wprojb, *xT;
    float *attn, *sumsq, *bias3;
    cudaGetSymbolAddress((void**)&xT,     g_xT);
    cudaGetSymbolAddress((void**)&qkvb,   g_qkvb);
    cudaGetSymbolAddress((void**)&attn,   g_attn);
    cudaGetSymbolAddress((void**)&attnb,  g_attnb);
    cudaGetSymbolAddress((void**)&w2,     g_w2);
    cudaGetSymbolAddress((void**)&w3,     g_w3);
    cudaGetSymbolAddress((void**)&wqkvb,  g_wqkv);
    cudaGetSymbolAddress((void**)&wprojb, g_wproj);
    cudaGetSymbolAddress((void**)&sumsq,  g_sumsq);
    cudaGetSymbolAddress((void**)&bias3,  g_bias3);

    const long sQKV = (long)TC2 * NPAD;
    const long sNC  = (long)NPAD * CCH;
    const long sATT = (long)CCH * CCH;
    const long sOUT = (long)CCH * HN;

    // 0) prep
    cudaMemsetAsync(sumsq, 0, (size_t)BATCH * 2 * CCH * sizeof(float));
    f2b2<<<(3*CCH*CCH + CCH*CCH + 255)/256, 256>>>(w_qkv, 3*CCH*CCH, w_proj, CCH*CCH);
    prep_xT<<<dim3(HN/64, CCH/64, BATCH), 256>>>(x, gamma, beta, mean, var);

    // 1) q,k = wqkv[0:768] . xT^T + b_qkv (NT, M=768) + fused sum-of-squares
    bgemm<1, true, true, false, true, false, true>
        <<<dim3(NPAD/128, TC2/128, BATCH), 256>>>(
        wqkvb, xT, qkvb, b_qkv, nullptr,
        CCH, CCH, CCH, NPAD, HN, 0, sNC, sQKV, 0, 0, 0);

    // 2) logits partials: split-K=2 (NT, fp32 partials)
    bgemm<KSPL, true, false, false, false, false, false>
        <<<dim3(CCH/128, CCH/128, BATCH*KSPL), 256>>>(
        qkvb, qkvb + (size_t)CCH*NPAD, attn, nullptr, nullptr,
        KCH, NPAD, NPAD, CCH, CCH, sQKV, sQKV, sATT, 0, (long)PSTR, 0);

    // 3) softmax -> bf16
    softmax_rows<<<dim3(CCH, BATCH), 128>>>(temp);

    // 4) W2[o,d] = wproj[o,:] . attn[:,d]   (NN, 384^3), bf16
    bgemm<1, false, false, false, true, false, false>
        <<<dim3(CCH/128, CCH/128, BATCH), 256>>>(
        wprojb, attnb, w2, nullptr, nullptr,
        CCH, CCH, CCH, CCH, CCH, 0, sATT, sATT, 0, 0, 0);

    // 5) W3[o,c] = W2[o,:] . Wv[:,c]   (NN, 384^3), bf16
    bgemm<1, false, false, false, true, false, false>
        <<<dim3(CCH/128, CCH/128, BATCH), 256>>>(
        w2, wqkvb + (size_t)2*CCH*CCH, w3, nullptr, nullptr,
        CCH, CCH, CCH, CCH, CCH, sATT, 0, sATT, 0, 0, 0);

    // 5b) bias3 = b_proj + W2 @ b_v  (parallel reduction per row)
    bias3_kernel<<<BATCH*CCH, 128>>>(b_proj, b_qkv);

    // 6) out[o,n] = W3[o,:] . xT[n,:] + bias3 + x   (NT, fp32, guarded)
    bgemm<1, true, true, true, false, true, false>
        <<<dim3(NPAD/128, CCH/128, BATCH), 256>>>(
        w3, xT, out, bias3, x,
        CCH, CCH, CCH, HN, HN, sATT, sNC, sOUT, sOUT, 0, CCH);
}

// round 14
// speedup vs baseline: 1.4669x; 1.2423x over previous
#include <cuda_runtime.h>
#include <cuda_bf16.h>
#include <math.h>

#define BATCH 16
#define CCH   384
#define HN    3136
#define NPAD  3200          // padded n-width for final GEMM
#define KSPL  2             // split-K for Gram GEMM (3136 = 2*1568)
#define KCH   1568
#define PSTR  ((size_t)BATCH * CCH * CCH)   // Gram partial-buffer stride

// ---------------- scratch (device globals, zero-initialized) ----------------
__device__ __nv_bfloat16 g_xnb  [(size_t)BATCH * CCH * NPAD];  // BN(x) bf16 [b][c][n] ld=NPAD (pad cols 0)
__device__ float         g_attn [KSPL * PSTR];                 // Gram partials fp32, then L0
__device__ __nv_bfloat16 g_Gb   [(size_t)BATCH * CCH * CCH];   // Gram bf16 (symmetric)
__device__ __nv_bfloat16 g_P    [(size_t)BATCH * 2 * CCH * CCH]; // P=[Wq;Wk]@G bf16 [768][384]
__device__ __nv_bfloat16 g_attnb[(size_t)BATCH * CCH * CCH];   // softmax bf16 [c][d]
__device__ __nv_bfloat16 g_w2   [(size_t)BATCH * CCH * CCH];   // W2 = wproj@attn
__device__ __nv_bfloat16 g_w3   [(size_t)BATCH * CCH * CCH];   // W3 = W2@Wv
__device__ float         g_bias3[BATCH * CCH];                 // b_proj + W2@b_v
__device__ __nv_bfloat16 g_wqkv [3 * CCH * CCH];
__device__ __nv_bfloat16 g_wproj[CCH * CCH];
__device__ float g_sumsq[BATCH * 2 * CCH];                     // ||q_c||^2, ||k_c||^2
__device__ float g_tvec [BATCH * 2 * CCH];                     // W@s per row
__device__ float g_s    [BATCH * CCH];                         // row sums of xn

// ---------------- helpers ----------------
__device__ __forceinline__ unsigned su32(const void* p) {
    return (unsigned)__cvta_generic_to_shared(p);
}
__device__ __forceinline__ unsigned pk(float a, float b) {
    __nv_bfloat162 h = __floats2bfloat162_rn(a, b);
    return *(unsigned*)&h;
}
__device__ __forceinline__ void mma_bf16(float* d, const unsigned* a, unsigned b0, unsigned b1) {
    asm volatile(
        "mma.sync.aligned.m16n8k16.row.col.f32.bf16.bf16.f32 "
        "{%0,%1,%2,%3}, {%4,%5,%6,%7}, {%8,%9}, {%0,%1,%2,%3};\n"
        : "+f"(d[0]), "+f"(d[1]), "+f"(d[2]), "+f"(d[3])
        : "r"(a[0]), "r"(a[1]), "r"(a[2]), "r"(a[3]), "r"(b0), "r"(b1));
}
#define LDSM4(r0,r1,r2,r3,addr) \
    asm volatile("ldmatrix.sync.aligned.m8n8.x4.shared.b16 {%0,%1,%2,%3}, [%4];" \
        : "=r"(r0),"=r"(r1),"=r"(r2),"=r"(r3) : "r"(addr))
#define LDSM4T(r0,r1,r2,r3,addr) \
    asm volatile("ldmatrix.sync.aligned.m8n8.x4.trans.shared.b16 {%0,%1,%2,%3}, [%4];" \
        : "=r"(r0),"=r"(r1),"=r"(r2),"=r"(r3) : "r"(addr))
#define CP16(dst, src) \
    asm volatile("cp.async.cg.shared.global [%0], [%1], 16;" :: "r"(dst), "l"(src))
#define CP_COMMIT() asm volatile("cp.async.commit_group;" ::: "memory")
#define CP_WAIT1()  asm volatile("cp.async.wait_group 1;" ::: "memory")

#define STAGE_BYTES 16384

// ============================================================
// bf16 GEMM (mma.sync), block 128x128xK32, 3-stage cp.async ring,
// 256 thr = 8 warps (4M x 2N), warp tile 32x64. (Proven R8 geometry.)
// ============================================================
template<int KSP, bool TRB, bool BIAS, bool RES, bool OUTBF, bool GUARDN>
__global__ __launch_bounds__(256, 2)
void bgemm(const __nv_bfloat16* __restrict__ A, const __nv_bfloat16* __restrict__ B,
           void* __restrict__ Cv, const float* __restrict__ bias,
           const float* __restrict__ res,
           int K, int lda, int ldb, int ldc, int nvalid,
           long sA, long sB, long sC, long sR, long sPart, long sBias)
{
    __shared__ __align__(16) unsigned char smem[3 * STAGE_BYTES];
    const unsigned sbase = su32(smem);

    const int tid = threadIdx.x;
    const int wid = tid >> 5, lane = tid & 31;
    const int wm = wid >> 1, wn = wid & 1;
    const int grp = lane >> 2, qd = lane & 3;
    const int row0 = blockIdx.y * 128;
    const int col0 = blockIdx.x * 128;
    int z = blockIdx.z;
    int part = 0;
    if (KSP > 1) { part = z % KSP; z /= KSP; }

    const __nv_bfloat16* Az = A + (size_t)z * sA + (size_t)part * K;
    const __nv_bfloat16* Bz = B + (size_t)z * sB + (size_t)part * K;
    const __nv_bfloat16* Ab = Az + (size_t)row0 * lda;
    const __nv_bfloat16* Bb = TRB ? (Bz + (size_t)col0 * ldb) : (Bz + col0);

    const int lr = tid >> 2, lc = tid & 3;
    const unsigned aoff1 = (unsigned)(lr * 64 + ((lc ^ ((lr >> 1) & 3)) * 16));
    const int lr2 = lr + 64;
    const unsigned aoff2 = (unsigned)(lr2 * 64 + ((lc ^ ((lr2 >> 1) & 3)) * 16));

    const int nk1 = tid >> 4, nc1 = tid & 15;
    const unsigned nboff1 = (unsigned)((nc1 >> 3) * 4096 + nk1 * 128 + (((nc1 & 7) ^ (nk1 & 7)) * 16));
    const int nk2 = (tid + 256) >> 4, nc2 = tid & 15;
    const unsigned nboff2 = (unsigned)((nc2 >> 3) * 4096 + nk2 * 128 + (((nc2 & 7) ^ (nk2 & 7)) * 16));

    const int T = K >> 5;

    int arow_l[2];
    #pragma unroll
    for (int mi = 0; mi < 2; mi++) arow_l[mi] = wm * 32 + mi * 16 + (lane & 15);
    const int achk = lane >> 4;
    const int bn_base = wn * 64 + ((lane >> 4) << 3) + (lane & 7);
    const int boct = (lane >> 3) & 1;
    const int nn_kl = lane & 15;
    const int nn_ch = lane >> 4;

    float acc[2][8][4] = {};

    auto issue = [&](int s, int k0) {
        const unsigned sa = sbase + s * STAGE_BYTES;
        const unsigned sb = sa + 8192;
        CP16(sa + aoff1, Ab + (size_t)lr  * lda + k0 + lc * 8);
        CP16(sa + aoff2, Ab + (size_t)lr2 * lda + k0 + lc * 8);
        if (TRB) {
            CP16(sb + aoff1, Bb + (size_t)lr  * ldb + k0 + lc * 8);
            CP16(sb + aoff2, Bb + (size_t)lr2 * ldb + k0 + lc * 8);
        } else {
            CP16(sb + nboff1, Bb + (size_t)(k0 + nk1) * ldb + nc1 * 8);
            CP16(sb + nboff2, Bb + (size_t)(k0 + nk2) * ldb + nc2 * 8);
        }
        CP_COMMIT();
    };

    issue(0, 0);
    issue(1, 32);

    for (int t = 0; t < T; t++) {
        CP_WAIT1();
        __syncthreads();

        if (t + 2 < T) issue((t + 2) % 3, (t + 2) << 5);
        else CP_COMMIT();

        const unsigned sa = sbase + (t % 3) * STAGE_BYTES;
        const unsigned sb = sa + 8192;

        #pragma unroll
        for (int ks = 0; ks < 2; ks++) {
            unsigned af[2][4];
            #pragma unroll
            for (int mi = 0; mi < 2; mi++) {
                unsigned addr = sa + arow_l[mi] * 64 +
                    (((ks * 2 + achk) ^ ((arow_l[mi] >> 1) & 3)) * 16);
                LDSM4(af[mi][0], af[mi][1], af[mi][2], af[mi][3], addr);
            }
            unsigned bq[4][4];
            if (TRB) {
                #pragma unroll
                for (int nj = 0; nj < 4; nj++) {
                    int nl = bn_base + nj * 16;
                    unsigned addr = sb + nl * 64 +
                        (((ks * 2 + boct) ^ ((nl >> 1) & 3)) * 16);
                    LDSM4(bq[nj][0], bq[nj][1], bq[nj][2], bq[nj][3], addr);
                }
            } else {
                const int kl = ks * 16 + nn_kl;
                const unsigned sbh = sb + wn * 4096 + kl * 128;
                #pragma unroll
                for (int nj = 0; nj < 4; nj++) {
                    unsigned addr = sbh + (((nj * 2 + nn_ch) ^ (kl & 7)) * 16);
                    LDSM4T(bq[nj][0], bq[nj][1], bq[nj][2], bq[nj][3], addr);
                }
            }
            #pragma unroll
            for (int nj = 0; nj < 4; nj++) {
                #pragma unroll
                for (int p = 0; p < 2; p++) {
                    unsigned b0 = bq[nj][p * 2], b1 = bq[nj][p * 2 + 1];
                    const int ni = nj * 2 + p;
                    #pragma unroll
                    for (int mi = 0; mi < 2; mi++)
                        mma_bf16(acc[mi][ni], af[mi], b0, b1);
                }
            }
        }
    }

    // ---- epilogue ----
    #pragma unroll
    for (int mi = 0; mi < 2; mi++) {
        const int r0 = row0 + wm * 32 + mi * 16 + grp;
        const int r1 = r0 + 8;
        float bv0 = 0.0f, bv1 = 0.0f;
        if (BIAS) {
            const float* bp = bias + (size_t)z * sBias;
            bv0 = bp[r0]; bv1 = bp[r1];
        }
        #pragma unroll
        for (int ni = 0; ni < 8; ni++) {
            const int c = col0 + wn * 64 + ni * 8 + 2 * qd;
            if (GUARDN && c >= nvalid) continue;
            float d0 = acc[mi][ni][0] + bv0, d1 = acc[mi][ni][1] + bv0;
            float d2 = acc[mi][ni][2] + bv1, d3 = acc[mi][ni][3] + bv1;
            if (RES) {
                const float* rp = res + (size_t)z * sR;
                float2 q0 = *(const float2*)&rp[(size_t)r0 * ldc + c];
                float2 q1 = *(const float2*)&rp[(size_t)r1 * ldc + c];
                d0 += q0.x; d1 += q0.y; d2 += q1.x; d3 += q1.y;
            }
            if (OUTBF) {
                __nv_bfloat16* Cb = (__nv_bfloat16*)Cv + (size_t)z * sC;
                *(unsigned*)&Cb[(size_t)r0 * ldc + c] = pk(d0, d1);
                *(unsigned*)&Cb[(size_t)r1 * ldc + c] = pk(d2, d3);
            } else {
                float* Cf = (float*)Cv + (size_t)z * sC + (size_t)part * sPart;
                *(float2*)&Cf[(size_t)r0 * ldc + c] = make_float2(d0, d1);
                *(float2*)&Cf[(size_t)r1 * ldc + c] = make_float2(d2, d3);
            }
        }
    }
}

// ---------------- prep / elementwise ----------------
__global__ void f2b2(const float* __restrict__ s1, int n1,
                     const float* __restrict__ s2, int n2) {
    int i = blockIdx.x * 256 + threadIdx.x;
    if (i < n1) g_wqkv[i] = __float2bfloat16(s1[i]);
    else if (i < n1 + n2) g_wproj[i - n1] = __float2bfloat16(s2[i - n1]);
}

// BN(x) elementwise -> xnb [b][c][n] bf16 (same layout, ld NPAD). 8 elems/thread.
__global__ __launch_bounds__(256)
void prep_xn(const float* __restrict__ x,
             const float* __restrict__ gamma, const float* __restrict__ beta,
             const float* __restrict__ mean,  const float* __restrict__ var) {
    const int idx = blockIdx.x * 256 + threadIdx.x;
    if (idx >= BATCH * CCH * (HN / 8)) return;
    const int n8 = idx % (HN / 8);
    const int bc = idx / (HN / 8);           // b*CCH + c
    const int c = bc % CCH;
    const float s = gamma[c] * rsqrtf(var[c] + 1e-5f);
    const float h = beta[c] - mean[c] * s;
    const float* src = x + (size_t)bc * HN + n8 * 8;
    float4 v0 = *(const float4*)src;
    float4 v1 = *(const float4*)(src + 4);
    uint4 o;
    o.x = pk(v0.x * s + h, v0.y * s + h);
    o.y = pk(v0.z * s + h, v0.w * s + h);
    o.z = pk(v1.x * s + h, v1.y * s + h);
    o.w = pk(v1.z * s + h, v1.w * s + h);
    *(uint4*)(g_xnb + (size_t)bc * NPAD + n8 * 8) = o;
}

// s[b][c] = sum_n xnb[b][c][n]
__global__ __launch_bounds__(128)
void rowsum() {
    const int b = blockIdx.y, c = blockIdx.x;
    const __nv_bfloat16* row = g_xnb + ((size_t)b * CCH + c) * NPAD;
    const int tid = threadIdx.x;
    __shared__ float red[128];
    float s = 0.0f;
    for (int i = tid; i < HN / 8; i += 128) {
        uint4 v = *(const uint4*)(row + i * 8);
        const __nv_bfloat162* h = (const __nv_bfloat162*)&v;
        #pragma unroll
        for (int j = 0; j < 4; j++) {
            float2 f = __bfloat1622float2(h[j]);
            s += f.x + f.y;
        }
    }
    red[tid] = s;
    __syncthreads();
    for (int st = 64; st > 0; st >>= 1) {
        if (tid < st) red[tid] += red[tid + st];
        __syncthreads();
    }
    if (tid == 0) g_s[b * CCH + c] = red[0];
}

// G bf16 = partial0 + partial1
__global__ void g2bf() {
    size_t i = (size_t)blockIdx.x * 256 + threadIdx.x;
    if (i < PSTR)
        g_Gb[i] = __float2bfloat16(g_attn[i] + g_attn[i + PSTR]);
}

// per-row stats: norm^2 = diag(P W^T) + 2b(Ws) + HN b^2 ; tvec = W@s
__global__ __launch_bounds__(128)
void qk_stats(const float* __restrict__ b_qkv) {
    const int b = blockIdx.y, r = blockIdx.x;   // r in [0,768)
    const __nv_bfloat16* w = g_wqkv + (size_t)r * CCH;
    const __nv_bfloat16* p = g_P + ((size_t)b * 2 * CCH + r) * CCH;
    const float* s = g_s + b * CCH;
    const int tid = threadIdx.x;
    __shared__ float r1[128], r2[128];
    float a1 = 0.0f, a2 = 0.0f;
    #pragma unroll
    for (int j = 0; j < 3; j++) {
        int e = tid + j * 128;
        float wv = __bfloat162float(w[e]);
        a1 += wv * __bfloat162float(p[e]);
        a2 += wv * s[e];
    }
    r1[tid] = a1; r2[tid] = a2;
    __syncthreads();
    for (int st = 64; st > 0; st >>= 1) {
        if (tid < st) { r1[tid] += r1[tid + st]; r2[tid] += r2[tid + st]; }
        __syncthreads();
    }
    if (tid == 0) {
        float bias = b_qkv[r];
        g_sumsq[b * 2 * CCH + r] = r1[0] + 2.0f * bias * r2[0] + (float)HN * bias * bias;
        g_tvec [b * 2 * CCH + r] = r2[0];
    }
}

// softmax: logits = L0 + bias corrections, scaled by t*invq*invk
__global__ __launch_bounds__(128)
void softmax_rows(const float* __restrict__ tptr, const float* __restrict__ b_qkv) {
    const int b = blockIdx.y, cc = blockIdx.x;
    const float* L = g_attn + ((size_t)b * CCH + cc) * CCH;
    __nv_bfloat16* orow = g_attnb + ((size_t)b * CCH + cc) * CCH;
    const int tid = threadIdx.x;
    __shared__ float red[128];

    const float* ssq = g_sumsq + (size_t)b * 2 * CCH;
    const float* tv  = g_tvec  + (size_t)b * 2 * CCH;
    const float bqv = b_qkv[cc];
    const float tqv = tv[cc];
    const float tsc = tptr[0] / fmaxf(sqrtf(ssq[cc]), 1e-12f);

    float v[3];
    #pragma unroll
    for (int j = 0; j < 3; j++) {
        int d = tid + j * 128;
        float bk = b_qkv[CCH + d];
        float tk = tv[CCH + d];
        float ik = 1.0f / fmaxf(sqrtf(ssq[CCH + d]), 1e-12f);
        float logit = L[d] + bqv * tk + bk * tqv + (float)HN * bqv * bk;
        v[j] = logit * tsc * ik;
    }

    float m = fmaxf(v[0], fmaxf(v[1], v[2]));
    red[tid] = m;
    __syncthreads();
    for (int st = 64; st > 0; st >>= 1) {
        if (tid < st) red[tid] = fmaxf(red[tid], red[tid + st]);
        __syncthreads();
    }
    m = red[0];
    __syncthreads();

    float e0 = expf(v[0] - m), e1 = expf(v[1] - m), e2 = expf(v[2] - m);
    red[tid] = e0 + e1 + e2;
    __syncthreads();
    for (int st = 64; st > 0; st >>= 1) {
        if (tid < st) red[tid] += red[tid + st];
        __syncthreads();
    }
    float inv = 1.0f / red[0];

    orow[tid]       = __float2bfloat16(e0 * inv);
    orow[tid + 128] = __float2bfloat16(e1 * inv);
    orow[tid + 256] = __float2bfloat16(e2 * inv);
}

// bias3[b][o] = b_proj[o] + sum_d W2[b][o][d] * b_qkv[2C+d]
__global__ __launch_bounds__(128)
void bias3_kernel(const float* __restrict__ b_proj, const float* __restrict__ b_qkv) {
    const int row = blockIdx.x;
    const __nv_bfloat16* w2row = g_w2 + (size_t)row * CCH;
    const float* bv = b_qkv + 2 * CCH;
    const int tid = threadIdx.x;
    __shared__ float red[128];

    float s = __bfloat162float(w2row[tid])       * bv[tid]
            + __bfloat162float(w2row[tid + 128]) * bv[tid + 128]
            + __bfloat162float(w2row[tid + 256]) * bv[tid + 256];
    red[tid] = s;
    __syncthreads();
    for (int st = 64; st > 0; st >>= 1) {
        if (tid < st) red[tid] += red[tid + st];
        __syncthreads();
    }
    if (tid == 0)
        g_bias3[row] = b_proj[row % CCH] + red[0];
}

// ---------------- host ----------------
extern "C" void kernel_launch(void* const* d_in, const int* in_sizes, int n_in,
                              void* d_out, int out_size)
{
    const float* x      = (const float*)d_in[0];
    const float* w_qkv  = (const float*)d_in[1];
    const float* b_qkv  = (const float*)d_in[2];
    const float* w_proj = (const float*)d_in[3];
    const float* b_proj = (const float*)d_in[4];
    const float* gamma  = (const float*)d_in[5];
    const float* beta   = (const float*)d_in[6];
    const float* mean   = (const float*)d_in[7];
    const float* var    = (const float*)d_in[8];
    const float* temp   = (const float*)d_in[9];
    float* out = (float*)d_out;

    __nv_bfloat16 *xnb, *Gb, *P, *attnb, *w2, *w3, *wqkvb, *wprojb;
    float *attn;
    cudaGetSymbolAddress((void**)&xnb,    g_xnb);
    cudaGetSymbolAddress((void**)&Gb,     g_Gb);
    cudaGetSymbolAddress((void**)&P,      g_P);
    cudaGetSymbolAddress((void**)&attn,   g_attn);
    cudaGetSymbolAddress((void**)&attnb,  g_attnb);
    cudaGetSymbolAddress((void**)&w2,     g_w2);
    cudaGetSymbolAddress((void**)&w3,     g_w3);
    cudaGetSymbolAddress((void**)&wqkvb,  g_wqkv);
    cudaGetSymbolAddress((void**)&wprojb, g_wproj);
    float *bias3;
    cudaGetSymbolAddress((void**)&bias3,  g_bias3);

    const long sXN  = (long)CCH * NPAD;
    const long sATT = (long)CCH * CCH;
    const long sP   = (long)2 * CCH * CCH;
    const long sOUT = (long)CCH * HN;

    // 0) prep
    f2b2<<<(3*CCH*CCH + CCH*CCH + 255)/256, 256>>>(w_qkv, 3*CCH*CCH, w_proj, CCH*CCH);
    prep_xn<<<(BATCH*CCH*(HN/8) + 255)/256, 256>>>(x, gamma, beta, mean, var);
    rowsum<<<dim3(CCH, BATCH), 128>>>();

    // 1) Gram partials: G = xn . xn^T (NT, K=3136, split-K=2, fp32 partials)
    bgemm<KSPL, true, false, false, false, false>
        <<<dim3(CCH/128, CCH/128, BATCH*KSPL), 256>>>(
        xnb, xnb, attn, nullptr, nullptr,
        KCH, NPAD, NPAD, CCH, CCH, sXN, sXN, sATT, 0, (long)PSTR, 0);

    // 2) reduce partials -> bf16 G
    g2bf<<<(int)((PSTR + 255)/256), 256>>>();

    // 3) P = [Wq;Wk] @ G  (NN, M=768, N=384, K=384), bf16
    bgemm<1, false, false, false, true, false>
        <<<dim3(CCH/128, 2*CCH/128, BATCH), 256>>>(
        wqkvb, Gb, P, nullptr, nullptr,
        CCH, CCH, CCH, CCH, CCH, 0, sATT, sP, 0, 0, 0);

    // 4) L0 = P_q @ Wk^T  (NT, 384^3), fp32 -> g_attn
    bgemm<1, true, false, false, false, false>
        <<<dim3(CCH/128, CCH/128, BATCH), 256>>>(
        P, wqkvb + (size_t)CCH*CCH, attn, nullptr, nullptr,
        CCH, CCH, CCH, CCH, CCH, sP, 0, sATT, 0, 0, 0);

    // 5) per-row norms + bias-correction vectors
    qk_stats<<<dim3(2*CCH, BATCH), 128>>>(b_qkv);

    // 6) softmax (bias-corrected logits, norms, temperature) -> bf16
    softmax_rows<<<dim3(CCH, BATCH), 128>>>(temp, b_qkv);

    // 7) W2 = wproj @ attn  (NN, 384^3), bf16
    bgemm<1, false, false, false, true, false>
        <<<dim3(CCH/128, CCH/128, BATCH), 256>>>(
        wprojb, attnb, w2, nullptr, nullptr,
        CCH, CCH, CCH, CCH, CCH, 0, sATT, sATT, 0, 0, 0);

    // 8) W3 = W2 @ Wv  (NN, 384^3), bf16
    bgemm<1, false, false, false, true, false>
        <<<dim3(CCH/128, CCH/128, BATCH), 256>>>(
        w2, wqkvb + (size_t)2*CCH*CCH, w3, nullptr, nullptr,
        CCH, CCH, CCH, CCH, CCH, sATT, 0, sATT, 0, 0, 0);

    // 9) bias3 = b_proj + W2 @ b_v
    bias3_kernel<<<BATCH*CCH, 128>>>(b_proj, b_qkv);

    // 10) out = W3 @ xn + bias3 + x  (NN, N=3200 guarded to 3136, fp32)
    bgemm<1, false, true, true, false, true>
        <<<dim3(NPAD/128, CCH/128, BATCH), 256>>>(
        w3, xnb, out, bias3, x,
        CCH, CCH, NPAD, HN, HN, sATT, sXN, sOUT, sOUT, 0, CCH);
}

// round 15
// speedup vs baseline: 1.5163x; 1.0337x over previous
#include <cuda_runtime.h>
#include <cuda_bf16.h>
#include <math.h>

#define BATCH 16
#define CCH   384
#define HN    3136
#define NPAD  3200          // padded n-width for final GEMM
#define KSPL  2             // split-K for Gram GEMM (3136 = 2*1568)
#define KCH   1568
#define PSTR  ((size_t)BATCH * CCH * CCH)   // Gram partial-buffer stride

// ---------------- scratch (device globals, zero-initialized) ----------------
__device__ __nv_bfloat16 g_xnb  [(size_t)BATCH * CCH * NPAD];    // BN(x) bf16 [b][c][n] ld=NPAD (pad cols 0)
__device__ float         g_attn [KSPL * PSTR];                   // Gram partials fp32, then L0
__device__ __nv_bfloat16 g_P    [(size_t)BATCH * 2 * CCH * CCH]; // P=[Wq;Wk]@G bf16 [768][384]
__device__ __nv_bfloat16 g_attnb[(size_t)BATCH * CCH * CCH];     // softmax bf16 [c][d]
__device__ __nv_bfloat16 g_w2   [(size_t)BATCH * CCH * CCH];     // W2 = wproj@attn
__device__ __nv_bfloat16 g_w3   [(size_t)BATCH * CCH * CCH];     // W3 = W2@Wv
__device__ float         g_bias3[BATCH * CCH];                   // b_proj + W2@b_v (seeded + atomics)
__device__ __nv_bfloat16 g_wqkv [3 * CCH * CCH];
__device__ __nv_bfloat16 g_wproj[CCH * CCH];
__device__ float g_sumsq[BATCH * 2 * CCH];                       // ||q_c||^2, ||k_c||^2
__device__ float g_tvec [BATCH * 2 * CCH];                       // W@s per row
__device__ float g_s    [BATCH * CCH];                           // row sums of xn

// ---------------- helpers ----------------
__device__ __forceinline__ unsigned su32(const void* p) {
    return (unsigned)__cvta_generic_to_shared(p);
}
__device__ __forceinline__ unsigned pk(float a, float b) {
    __nv_bfloat162 h = __floats2bfloat162_rn(a, b);
    return *(unsigned*)&h;
}
__device__ __forceinline__ void mma_bf16(float* d, const unsigned* a, unsigned b0, unsigned b1) {
    asm volatile(
        "mma.sync.aligned.m16n8k16.row.col.f32.bf16.bf16.f32 "
        "{%0,%1,%2,%3}, {%4,%5,%6,%7}, {%8,%9}, {%0,%1,%2,%3};\n"
        : "+f"(d[0]), "+f"(d[1]), "+f"(d[2]), "+f"(d[3])
        : "r"(a[0]), "r"(a[1]), "r"(a[2]), "r"(a[3]), "r"(b0), "r"(b1));
}
#define LDSM4(r0,r1,r2,r3,addr) \
    asm volatile("ldmatrix.sync.aligned.m8n8.x4.shared.b16 {%0,%1,%2,%3}, [%4];" \
        : "=r"(r0),"=r"(r1),"=r"(r2),"=r"(r3) : "r"(addr))
#define LDSM4T(r0,r1,r2,r3,addr) \
    asm volatile("ldmatrix.sync.aligned.m8n8.x4.trans.shared.b16 {%0,%1,%2,%3}, [%4];" \
        : "=r"(r0),"=r"(r1),"=r"(r2),"=r"(r3) : "r"(addr))
#define CP16(dst, src) \
    asm volatile("cp.async.cg.shared.global [%0], [%1], 16;" :: "r"(dst), "l"(src))
#define CP_COMMIT() asm volatile("cp.async.commit_group;" ::: "memory")
#define CP_WAIT1()  asm volatile("cp.async.wait_group 1;" ::: "memory")
#define STS128U(addr, v) \
    asm volatile("st.shared.v4.b32 [%0], {%1,%2,%3,%4};" \
        :: "r"(addr), "r"((v).x), "r"((v).y), "r"((v).z), "r"((v).w))

#define STAGE_BYTES 16384

// ============================================================
// bf16 GEMM (mma.sync), block 128x128xK32, 3-stage cp.async ring,
// 256 thr = 8 warps (4M x 2N), warp tile 32x64. (Proven R8 geometry.)
// BSUM: B operand built on-the-fly as bf16(partial0+partial1) from fp32
//       (NN path only; B ptr is cast to const float*, ldb in floats).
// DOT:  epilogue accumulates sum_c D[r,c]*bias[c] into g_bias3[z*CCH+r]
//       via quad shuffle-reduce + atomicAdd (bias = dot vector).
// ============================================================
template<int KSP, bool TRB, bool BSUM, bool BIAS, bool RES, bool OUTBF, bool GUARDN, bool DOT>
__global__ __launch_bounds__(256, 2)
void bgemm(const __nv_bfloat16* __restrict__ A, const __nv_bfloat16* __restrict__ B,
           void* __restrict__ Cv, const float* __restrict__ bias,
           const float* __restrict__ res,
           int K, int lda, int ldb, int ldc, int nvalid,
           long sA, long sB, long sC, long sR, long sPart, long sBias)
{
    __shared__ __align__(16) unsigned char smem[3 * STAGE_BYTES];
    const unsigned sbase = su32(smem);

    const int tid = threadIdx.x;
    const int wid = tid >> 5, lane = tid & 31;
    const int wm = wid >> 1, wn = wid & 1;
    const int grp = lane >> 2, qd = lane & 3;
    const int row0 = blockIdx.y * 128;
    const int col0 = blockIdx.x * 128;
    int z = blockIdx.z;
    int part = 0;
    if (KSP > 1) { part = z % KSP; z /= KSP; }

    const __nv_bfloat16* Az = A + (size_t)z * sA + (size_t)part * K;
    const __nv_bfloat16* Ab = Az + (size_t)row0 * lda;
    const __nv_bfloat16* Bb = nullptr;
    const float* BfB = nullptr;
    if (BSUM) {
        BfB = (const float*)B + (size_t)z * sB + col0;
    } else {
        const __nv_bfloat16* Bz = B + (size_t)z * sB + (size_t)part * K;
        Bb = TRB ? (Bz + (size_t)col0 * ldb) : (Bz + col0);
    }

    const int lr = tid >> 2, lc = tid & 3;
    const unsigned aoff1 = (unsigned)(lr * 64 + ((lc ^ ((lr >> 1) & 3)) * 16));
    const int lr2 = lr + 64;
    const unsigned aoff2 = (unsigned)(lr2 * 64 + ((lc ^ ((lr2 >> 1) & 3)) * 16));

    const int nk1 = tid >> 4, nc1 = tid & 15;
    const unsigned nboff1 = (unsigned)((nc1 >> 3) * 4096 + nk1 * 128 + (((nc1 & 7) ^ (nk1 & 7)) * 16));
    const int nk2 = (tid + 256) >> 4, nc2 = tid & 15;
    const unsigned nboff2 = (unsigned)((nc2 >> 3) * 4096 + nk2 * 128 + (((nc2 & 7) ^ (nk2 & 7)) * 16));

    const int T = K >> 5;

    int arow_l[2];
    #pragma unroll
    for (int mi = 0; mi < 2; mi++) arow_l[mi] = wm * 32 + mi * 16 + (lane & 15);
    const int achk = lane >> 4;
    const int bn_base = wn * 64 + ((lane >> 4) << 3) + (lane & 7);
    const int boct = (lane >> 3) & 1;
    const int nn_kl = lane & 15;
    const int nn_ch = lane >> 4;

    float acc[2][8][4] = {};

    auto issue = [&](int s, int k0) {
        const unsigned sa = sbase + s * STAGE_BYTES;
        const unsigned sb = sa + 8192;
        CP16(sa + aoff1, Ab + (size_t)lr  * lda + k0 + lc * 8);
        CP16(sa + aoff2, Ab + (size_t)lr2 * lda + k0 + lc * 8);
        if (BSUM) {
            const float* p1 = BfB + (size_t)(k0 + nk1) * ldb + nc1 * 8;
            float4 u0 = *(const float4*)p1,        u1 = *(const float4*)(p1 + 4);
            float4 v0 = *(const float4*)(p1 + PSTR), v1 = *(const float4*)(p1 + 4 + PSTR);
            uint4 o1;
            o1.x = pk(u0.x + v0.x, u0.y + v0.y);
            o1.y = pk(u0.z + v0.z, u0.w + v0.w);
            o1.z = pk(u1.x + v1.x, u1.y + v1.y);
            o1.w = pk(u1.z + v1.z, u1.w + v1.w);
            STS128U(sb + nboff1, o1);
            const float* p2 = BfB + (size_t)(k0 + nk2) * ldb + nc2 * 8;
            float4 w0 = *(const float4*)p2,        w1 = *(const float4*)(p2 + 4);
            float4 x0 = *(const float4*)(p2 + PSTR), x1 = *(const float4*)(p2 + 4 + PSTR);
            uint4 o2;
            o2.x = pk(w0.x + x0.x, w0.y + x0.y);
            o2.y = pk(w0.z + x0.z, w0.w + x0.w);
            o2.z = pk(w1.x + x1.x, w1.y + x1.y);
            o2.w = pk(w1.z + x1.z, w1.w + x1.w);
            STS128U(sb + nboff2, o2);
        } else if (TRB) {
            CP16(sb + aoff1, Bb + (size_t)lr  * ldb + k0 + lc * 8);
            CP16(sb + aoff2, Bb + (size_t)lr2 * ldb + k0 + lc * 8);
        } else {
            CP16(sb + nboff1, Bb + (size_t)(k0 + nk1) * ldb + nc1 * 8);
            CP16(sb + nboff2, Bb + (size_t)(k0 + nk2) * ldb + nc2 * 8);
        }
        CP_COMMIT();
    };

    issue(0, 0);
    issue(1, 32);

    for (int t = 0; t < T; t++) {
        CP_WAIT1();
        __syncthreads();

        if (t + 2 < T) issue((t + 2) % 3, (t + 2) << 5);
        else CP_COMMIT();

        const unsigned sa = sbase + (t % 3) * STAGE_BYTES;
        const unsigned sb = sa + 8192;

        #pragma unroll
        for (int ks = 0; ks < 2; ks++) {
            unsigned af[2][4];
            #pragma unroll
            for (int mi = 0; mi < 2; mi++) {
                unsigned addr = sa + arow_l[mi] * 64 +
                    (((ks * 2 + achk) ^ ((arow_l[mi] >> 1) & 3)) * 16);
                LDSM4(af[mi][0], af[mi][1], af[mi][2], af[mi][3], addr);
            }
            unsigned bq[4][4];
            if (TRB) {
                #pragma unroll
                for (int nj = 0; nj < 4; nj++) {
                    int nl = bn_base + nj * 16;
                    unsigned addr = sb + nl * 64 +
                        (((ks * 2 + boct) ^ ((nl >> 1) & 3)) * 16);
                    LDSM4(bq[nj][0], bq[nj][1], bq[nj][2], bq[nj][3], addr);
                }
            } else {
                const int kl = ks * 16 + nn_kl;
                const unsigned sbh = sb + wn * 4096 + kl * 128;
                #pragma unroll
                for (int nj = 0; nj < 4; nj++) {
                    unsigned addr = sbh + (((nj * 2 + nn_ch) ^ (kl & 7)) * 16);
                    LDSM4T(bq[nj][0], bq[nj][1], bq[nj][2], bq[nj][3], addr);
                }
            }
            #pragma unroll
            for (int nj = 0; nj < 4; nj++) {
                #pragma unroll
                for (int p = 0; p < 2; p++) {
                    unsigned b0 = bq[nj][p * 2], b1 = bq[nj][p * 2 + 1];
                    const int ni = nj * 2 + p;
                    #pragma unroll
                    for (int mi = 0; mi < 2; mi++)
                        mma_bf16(acc[mi][ni], af[mi], b0, b1);
                }
            }
        }
    }

    // ---- epilogue ----
    #pragma unroll
    for (int mi = 0; mi < 2; mi++) {
        const int r0 = row0 + wm * 32 + mi * 16 + grp;
        const int r1 = r0 + 8;
        float bv0 = 0.0f, bv1 = 0.0f;
        if (BIAS) {
            const float* bp = bias + (size_t)z * sBias;
            bv0 = bp[r0]; bv1 = bp[r1];
        }
        float s0 = 0.0f, s1 = 0.0f;
        #pragma unroll
        for (int ni = 0; ni < 8; ni++) {
            const int c = col0 + wn * 64 + ni * 8 + 2 * qd;
            if (GUARDN && c >= nvalid) continue;
            float d0 = acc[mi][ni][0] + bv0, d1 = acc[mi][ni][1] + bv0;
            float d2 = acc[mi][ni][2] + bv1, d3 = acc[mi][ni][3] + bv1;
            if (RES) {
                const float* rp = res + (size_t)z * sR;
                float2 q0 = *(const float2*)&rp[(size_t)r0 * ldc + c];
                float2 q1 = *(const float2*)&rp[(size_t)r1 * ldc + c];
                d0 += q0.x; d1 += q0.y; d2 += q1.x; d3 += q1.y;
            }
            if (DOT) {
                float w0 = bias[c], w1 = bias[c + 1];
                s0 += d0 * w0 + d1 * w1;
                s1 += d2 * w0 + d3 * w1;
            }
            if (OUTBF) {
                __nv_bfloat16* Cb = (__nv_bfloat16*)Cv + (size_t)z * sC;
                *(unsigned*)&Cb[(size_t)r0 * ldc + c] = pk(d0, d1);
                *(unsigned*)&Cb[(size_t)r1 * ldc + c] = pk(d2, d3);
            } else {
                float* Cf = (float*)Cv + (size_t)z * sC + (size_t)part * sPart;
                *(float2*)&Cf[(size_t)r0 * ldc + c] = make_float2(d0, d1);
                *(float2*)&Cf[(size_t)r1 * ldc + c] = make_float2(d2, d3);
            }
        }
        if (DOT) {
            s0 += __shfl_xor_sync(0xffffffffu, s0, 1);
            s0 += __shfl_xor_sync(0xffffffffu, s0, 2);
            s1 += __shfl_xor_sync(0xffffffffu, s1, 1);
            s1 += __shfl_xor_sync(0xffffffffu, s1, 2);
            if (qd == 0) {
                atomicAdd(&g_bias3[(size_t)z * CCH + r0], s0);
                atomicAdd(&g_bias3[(size_t)z * CCH + r1], s1);
            }
        }
    }
}

// ---------------- prep / elementwise ----------------
// weights -> bf16 + seed g_bias3 with b_proj (one launch)
__global__ void f2b2(const float* __restrict__ s1, int n1,
                     const float* __restrict__ s2, int n2,
                     const float* __restrict__ b_proj) {
    int i = blockIdx.x * 256 + threadIdx.x;
    if (i < n1) g_wqkv[i] = __float2bfloat16(s1[i]);
    else if (i < n1 + n2) g_wproj[i - n1] = __float2bfloat16(s2[i - n1]);
    else if (i < n1 + n2 + BATCH * CCH) {
        int j = i - n1 - n2;
        g_bias3[j] = b_proj[j % CCH];
    }
}

// BN(x) -> xnb bf16 + per-row sum. Block per (b,c) row, 256 threads.
__global__ __launch_bounds__(256)
void prep_xn(const float* __restrict__ x,
             const float* __restrict__ gamma, const float* __restrict__ beta,
             const float* __restrict__ mean,  const float* __restrict__ var) {
    const int b = blockIdx.y, c = blockIdx.x;
    const float s = gamma[c] * rsqrtf(var[c] + 1e-5f);
    const float h = beta[c] - mean[c] * s;
    const float* src = x + ((size_t)b * CCH + c) * HN;
    __nv_bfloat16* dst = g_xnb + ((size_t)b * CCH + c) * NPAD;
    const int tid = threadIdx.x;
    __shared__ float red[256];

    float acc = 0.0f;
    for (int i = tid; i < HN / 8; i += 256) {
        float4 v0 = *(const float4*)(src + i * 8);
        float4 v1 = *(const float4*)(src + i * 8 + 4);
        float f0 = v0.x * s + h, f1 = v0.y * s + h, f2 = v0.z * s + h, f3 = v0.w * s + h;
        float f4 = v1.x * s + h, f5 = v1.y * s + h, f6 = v1.z * s + h, f7 = v1.w * s + h;
        uint4 o;
        o.x = pk(f0, f1); o.y = pk(f2, f3); o.z = pk(f4, f5); o.w = pk(f6, f7);
        *(uint4*)(dst + i * 8) = o;
        acc += f0 + f1 + f2 + f3 + f4 + f5 + f6 + f7;
    }
    red[tid] = acc;
    __syncthreads();
    for (int st = 128; st > 0; st >>= 1) {
        if (tid < st) red[tid] += red[tid + st];
        __syncthreads();
    }
    if (tid == 0) g_s[b * CCH + c] = red[0];
}

// per-row stats: norm^2 = diag(P W^T) + 2b(Ws) + HN b^2 ; tvec = W@s
__global__ __launch_bounds__(128)
void qk_stats(const float* __restrict__ b_qkv) {
    const int b = blockIdx.y, r = blockIdx.x;   // r in [0,768)
    const __nv_bfloat16* w = g_wqkv + (size_t)r * CCH;
    const __nv_bfloat16* p = g_P + ((size_t)b * 2 * CCH + r) * CCH;
    const float* s = g_s + b * CCH;
    const int tid = threadIdx.x;
    __shared__ float r1[128], r2[128];
    float a1 = 0.0f, a2 = 0.0f;
    #pragma unroll
    for (int j = 0; j < 3; j++) {
        int e = tid + j * 128;
        float wv = __bfloat162float(w[e]);
        a1 += wv * __bfloat162float(p[e]);
        a2 += wv * s[e];
    }
    r1[tid] = a1; r2[tid] = a2;
    __syncthreads();
    for (int st = 64; st > 0; st >>= 1) {
        if (tid < st) { r1[tid] += r1[tid + st]; r2[tid] += r2[tid + st]; }
        __syncthreads();
    }
    if (tid == 0) {
        float bias = b_qkv[r];
        g_sumsq[b * 2 * CCH + r] = r1[0] + 2.0f * bias * r2[0] + (float)HN * bias * bias;
        g_tvec [b * 2 * CCH + r] = r2[0];
    }
}

// softmax: logits = L0 + bias corrections, scaled by t*invq*invk
__global__ __launch_bounds__(128)
void softmax_rows(const float* __restrict__ tptr, const float* __restrict__ b_qkv) {
    const int b = blockIdx.y, cc = blockIdx.x;
    const float* L = g_attn + ((size_t)b * CCH + cc) * CCH;
    __nv_bfloat16* orow = g_attnb + ((size_t)b * CCH + cc) * CCH;
    const int tid = threadIdx.x;
    __shared__ float red[128];

    const float* ssq = g_sumsq + (size_t)b * 2 * CCH;
    const float* tv  = g_tvec  + (size_t)b * 2 * CCH;
    const float bqv = b_qkv[cc];
    const float tqv = tv[cc];
    const float tsc = tptr[0] / fmaxf(sqrtf(ssq[cc]), 1e-12f);

    float v[3];
    #pragma unroll
    for (int j = 0; j < 3; j++) {
        int d = tid + j * 128;
        float bk = b_qkv[CCH + d];
        float tk = tv[CCH + d];
        float ik = 1.0f / fmaxf(sqrtf(ssq[CCH + d]), 1e-12f);
        float logit = L[d] + bqv * tk + bk * tqv + (float)HN * bqv * bk;
        v[j] = logit * tsc * ik;
    }

    float m = fmaxf(v[0], fmaxf(v[1], v[2]));
    red[tid] = m;
    __syncthreads();
    for (int st = 64; st > 0; st >>= 1) {
        if (tid < st) red[tid] = fmaxf(red[tid], red[tid + st]);
        __syncthreads();
    }
    m = red[0];
    __syncthreads();

    float e0 = expf(v[0] - m), e1 = expf(v[1] - m), e2 = expf(v[2] - m);
    red[tid] = e0 + e1 + e2;
    __syncthreads();
    for (int st = 64; st > 0; st >>= 1) {
        if (tid < st) red[tid] += red[tid + st];
        __syncthreads();
    }
    float inv = 1.0f / red[0];

    orow[tid]       = __float2bfloat16(e0 * inv);
    orow[tid + 128] = __float2bfloat16(e1 * inv);
    orow[tid + 256] = __float2bfloat16(e2 * inv);
}

// ---------------- host ----------------
extern "C" void kernel_launch(void* const* d_in, const int* in_sizes, int n_in,
                              void* d_out, int out_size)
{
    const float* x      = (const float*)d_in[0];
    const float* w_qkv  = (const float*)d_in[1];
    const float* b_qkv  = (const float*)d_in[2];
    const float* w_proj = (const float*)d_in[3];
    const float* b_proj = (const float*)d_in[4];
    const float* gamma  = (const float*)d_in[5];
    const float* beta   = (const float*)d_in[6];
    const float* mean   = (const float*)d_in[7];
    const float* var    = (const float*)d_in[8];
    const float* temp   = (const float*)d_in[9];
    float* out = (float*)d_out;

    __nv_bfloat16 *xnb, *P, *attnb, *w2, *w3, *wqkvb, *wprojb;
    float *attn, *bias3;
    cudaGetSymbolAddress((void**)&xnb,    g_xnb);
    cudaGetSymbolAddress((void**)&P,      g_P);
    cudaGetSymbolAddress((void**)&attn,   g_attn);
    cudaGetSymbolAddress((void**)&attnb,  g_attnb);
    cudaGetSymbolAddress((void**)&w2,     g_w2);
    cudaGetSymbolAddress((void**)&w3,     g_w3);
    cudaGetSymbolAddress((void**)&wqkvb,  g_wqkv);
    cudaGetSymbolAddress((void**)&wprojb, g_wproj);
    cudaGetSymbolAddress((void**)&bias3,  g_bias3);

    const long sXN  = (long)CCH * NPAD;
    const long sATT = (long)CCH * CCH;
    const long sP   = (long)2 * CCH * CCH;
    const long sOUT = (long)CCH * HN;

    // 0) prep: weights->bf16 + bias3 seed; BN(x)->bf16 + row sums
    f2b2<<<(3*CCH*CCH + CCH*CCH + BATCH*CCH + 255)/256, 256>>>(
        w_qkv, 3*CCH*CCH, w_proj, CCH*CCH, b_proj);
    prep_xn<<<dim3(CCH, BATCH), 256>>>(x, gamma, beta, mean, var);

    // 1) Gram partials: G = xn . xn^T (NT, K=3136, split-K=2, fp32 partials)
    bgemm<KSPL, true, false, false, false, false, false, false>
        <<<dim3(CCH/128, CCH/128, BATCH*KSPL), 256>>>(
        xnb, xnb, attn, nullptr, nullptr,
        KCH, NPAD, NPAD, CCH, CCH, sXN, sXN, sATT, 0, (long)PSTR, 0);

    // 2) P = [Wq;Wk] @ G  (NN, M=768, K=384; B = bf16(partial0+partial1) on the fly)
    bgemm<1, false, true, false, false, true, false, false>
        <<<dim3(CCH/128, 2*CCH/128, BATCH), 256>>>(
        wqkvb, (const __nv_bfloat16*)attn, P, nullptr, nullptr,
        CCH, CCH, CCH, CCH, CCH, 0, sATT, sP, 0, 0, 0);

    // 3) L0 = P_q @ Wk^T  (NT, 384^3), fp32 -> g_attn (overwrites partial0)
    bgemm<1, true, false, false, false, false, false, false>
        <<<dim3(CCH/128, CCH/128, BATCH), 256>>>(
        P, wqkvb + (size_t)CCH*CCH, attn, nullptr, nullptr,
        CCH, CCH, CCH, CCH, CCH, sP, 0, sATT, 0, 0, 0);

    // 4) per-row norms + bias-correction vectors
    qk_stats<<<dim3(2*CCH, BATCH), 128>>>(b_qkv);

    // 5) softmax (bias-corrected logits, norms, temperature) -> bf16
    softmax_rows<<<dim3(CCH, BATCH), 128>>>(temp, b_qkv);

    // 6) W2 = wproj @ attn (NN, 384^3), bf16 + fused bias3 dot (bias arg = b_v)
    bgemm<1, false, false, false, false, true, false, true>
        <<<dim3(CCH/128, CCH/128, BATCH), 256>>>(
        wprojb, attnb, w2, b_qkv + 2*CCH, nullptr,
        CCH, CCH, CCH, CCH, CCH, 0, sATT, sATT, 0, 0, 0);

    // 7) W3 = W2 @ Wv  (NN, 384^3), bf16
    bgemm<1, false, false, false, false, true, false, false>
        <<<dim3(CCH/128, CCH/128, BATCH), 256>>>(
        w2, wqkvb + (size_t)2*CCH*CCH, w3, nullptr, nullptr,
        CCH, CCH, CCH, CCH, CCH, sATT, 0, sATT, 0, 0, 0);

    // 8) out = W3 @ xn + bias3 + x  (NN, N=3200 guarded to 3136, fp32)
    bgemm<1, false, false, true, true, false, true, false>
        <<<dim3(NPAD/128, CCH/128, BATCH), 256>>>(
        w3, xnb, out, bias3, x,
        CCH, CCH, NPAD, HN, HN, sATT, sXN, sOUT, sOUT, 0, CCH);
}

// round 16
// speedup vs baseline: 1.5334x; 1.0113x over previous
#include <cuda_runtime.h>
#include <cuda_bf16.h>
#include <math.h>

#define BATCH 16
#define CCH   384
#define HN    3136
#define NPAD  3200          // padded n-width for final GEMM
#define KSPL  2             // split-K for Gram GEMM (3136 = 2*1568)
#define KCH   1568
#define PSTR  ((size_t)BATCH * CCH * CCH)   // Gram partial-buffer stride

// ---------------- scratch (device globals, zero-initialized) ----------------
__device__ __nv_bfloat16 g_xnb  [(size_t)BATCH * CCH * NPAD];    // BN(x) bf16 [b][c][n] ld=NPAD
__device__ float         g_attn [KSPL * PSTR];                   // Gram partials fp32, then L0
__device__ __nv_bfloat16 g_P    [(size_t)BATCH * 2 * CCH * CCH]; // P=[Wq;Wk]@G bf16 [768][384]
__device__ __nv_bfloat16 g_attnb[(size_t)BATCH * CCH * CCH];     // softmax bf16 [c][d]
__device__ __nv_bfloat16 g_w2   [(size_t)BATCH * CCH * CCH];     // W2 = wproj@attn
__device__ __nv_bfloat16 g_w3   [(size_t)BATCH * CCH * CCH];     // W3 = W2@Wv
__device__ float         g_bias3[BATCH * CCH];                   // b_proj + W2@b_v
__device__ __nv_bfloat16 g_wqkv [3 * CCH * CCH];
__device__ __nv_bfloat16 g_wproj[CCH * CCH];
__device__ float g_sumsq[BATCH * 2 * CCH];
__device__ float g_tvec [BATCH * 2 * CCH];
__device__ float g_s    [BATCH * CCH];

// ---------------- helpers ----------------
__device__ __forceinline__ unsigned su32(const void* p) {
    return (unsigned)__cvta_generic_to_shared(p);
}
__device__ __forceinline__ unsigned pk(float a, float b) {
    __nv_bfloat162 h = __floats2bfloat162_rn(a, b);
    return *(unsigned*)&h;
}
__device__ __forceinline__ void mma_bf16(float* d, const unsigned* a, unsigned b0, unsigned b1) {
    asm volatile(
        "mma.sync.aligned.m16n8k16.row.col.f32.bf16.bf16.f32 "
        "{%0,%1,%2,%3}, {%4,%5,%6,%7}, {%8,%9}, {%0,%1,%2,%3};\n"
        : "+f"(d[0]), "+f"(d[1]), "+f"(d[2]), "+f"(d[3])
        : "r"(a[0]), "r"(a[1]), "r"(a[2]), "r"(a[3]), "r"(b0), "r"(b1));
}
#define LDSM4(r0,r1,r2,r3,addr) \
    asm volatile("ldmatrix.sync.aligned.m8n8.x4.shared.b16 {%0,%1,%2,%3}, [%4];" \
        : "=r"(r0),"=r"(r1),"=r"(r2),"=r"(r3) : "r"(addr))
#define LDSM4T(r0,r1,r2,r3,addr) \
    asm volatile("ldmatrix.sync.aligned.m8n8.x4.trans.shared.b16 {%0,%1,%2,%3}, [%4];" \
        : "=r"(r0),"=r"(r1),"=r"(r2),"=r"(r3) : "r"(addr))
#define CP16(dst, src) \
    asm volatile("cp.async.cg.shared.global [%0], [%1], 16;" :: "r"(dst), "l"(src))
#define CP_COMMIT() asm volatile("cp.async.commit_group;" ::: "memory")
#define CP_WAIT1()  asm volatile("cp.async.wait_group 1;" ::: "memory")
#define STS128U(addr, v) \
    asm volatile("st.shared.v4.b32 [%0], {%1,%2,%3,%4};" \
        :: "r"(addr), "r"((v).x), "r"((v).y), "r"((v).z), "r"((v).w))

// ============================================================
// bf16 GEMM (mma.sync), block 128 x BN x K32, 3-stage cp.async ring,
// 256 thr = 8 warps (4M x 2N), warp tile 32 x (BN/2).
// BN=128: proven R8 geometry. BN=64: half-width tile (2x CTAs for 384-wide N).
// BSUM (BN=128 NN only): B built on the fly as bf16(partial0+partial1).
// DOT: epilogue accumulates sum_c D[r,c]*bias[c] -> g_bias3 (atomics).
// ============================================================
template<int KSP, int BN, bool TRB, bool BSUM, bool BIAS, bool RES, bool OUTBF, bool GUARDN, bool DOT>
__global__ __launch_bounds__(256, 2)
void bgemm(const __nv_bfloat16* __restrict__ A, const __nv_bfloat16* __restrict__ B,
           void* __restrict__ Cv, const float* __restrict__ bias,
           const float* __restrict__ res,
           int K, int lda, int ldb, int ldc, int nvalid,
           long sA, long sB, long sC, long sR, long sPart, long sBias)
{
    constexpr int NI   = BN / 16;                 // 8 or 4
    constexpr int BSZ  = (BN == 128) ? 8192 : 4096;
    constexpr int STG  = 8192 + BSZ;
    __shared__ __align__(16) unsigned char smem[3 * STG];
    const unsigned sbase = su32(smem);

    const int tid = threadIdx.x;
    const int wid = tid >> 5, lane = tid & 31;
    const int wm = wid >> 1, wn = wid & 1;
    const int grp = lane >> 2, qd = lane & 3;
    const int row0 = blockIdx.y * 128;
    const int col0 = blockIdx.x * BN;
    int z = blockIdx.z;
    int part = 0;
    if (KSP > 1) { part = z % KSP; z /= KSP; }

    const __nv_bfloat16* Az = A + (size_t)z * sA + (size_t)part * K;
    const __nv_bfloat16* Ab = Az + (size_t)row0 * lda;
    const __nv_bfloat16* Bb = nullptr;
    const float* BfB = nullptr;
    if (BSUM) {
        BfB = (const float*)B + (size_t)z * sB + col0;
    } else {
        const __nv_bfloat16* Bz = B + (size_t)z * sB + (size_t)part * K;
        Bb = TRB ? (Bz + (size_t)col0 * ldb) : (Bz + col0);
    }

    const int lr = tid >> 2, lc = tid & 3;
    const unsigned aoff1 = (unsigned)(lr * 64 + ((lc ^ ((lr >> 1) & 3)) * 16));
    const int lr2 = lr + 64;
    const unsigned aoff2 = (unsigned)(lr2 * 64 + ((lc ^ ((lr2 >> 1) & 3)) * 16));

    // NN loader geometry (BN=128: two 4KB halves; BN=64: one 4KB block)
    const int nk1 = tid >> 4, nc1 = tid & 15;
    const unsigned nboff1 = (unsigned)((nc1 >> 3) * 4096 + nk1 * 128 + (((nc1 & 7) ^ (nk1 & 7)) * 16));
    const int nk2 = (tid + 256) >> 4, nc2 = tid & 15;
    const unsigned nboff2 = (unsigned)((nc2 >> 3) * 4096 + nk2 * 128 + (((nc2 & 7) ^ (nk2 & 7)) * 16));
    const int nk64 = tid >> 3, nc64 = tid & 7;     // BN=64: 32 rows x 8 chunks
    const unsigned nboff64 = (unsigned)(nk64 * 128 + ((nc64 ^ (nk64 & 7)) * 16));

    const int T = K >> 5;

    int arow_l[2];
    #pragma unroll
    for (int mi = 0; mi < 2; mi++) arow_l[mi] = wm * 32 + mi * 16 + (lane & 15);
    const int achk = lane >> 4;
    const int bn_base = wn * (BN / 2) + ((lane >> 4) << 3) + (lane & 7);  // NT
    const int boct = (lane >> 3) & 1;                                     // NT
    const int nn_kl = lane & 15;                                          // NN
    const int nn_ch = lane >> 4;                                          // NN

    float acc[2][NI][4] = {};

    auto issue = [&](int s, int k0) {
        const unsigned sa = sbase + s * STG;
        const unsigned sb = sa + 8192;
        CP16(sa + aoff1, Ab + (size_t)lr  * lda + k0 + lc * 8);
        CP16(sa + aoff2, Ab + (size_t)lr2 * lda + k0 + lc * 8);
        if (BSUM) {
            const float* p1 = BfB + (size_t)(k0 + nk1) * ldb + nc1 * 8;
            float4 u0 = *(const float4*)p1,          u1 = *(const float4*)(p1 + 4);
            float4 v0 = *(const float4*)(p1 + PSTR), v1 = *(const float4*)(p1 + 4 + PSTR);
            uint4 o1;
            o1.x = pk(u0.x + v0.x, u0.y + v0.y);
            o1.y = pk(u0.z + v0.z, u0.w + v0.w);
            o1.z = pk(u1.x + v1.x, u1.y + v1.y);
            o1.w = pk(u1.z + v1.z, u1.w + v1.w);
            STS128U(sb + nboff1, o1);
            const float* p2 = BfB + (size_t)(k0 + nk2) * ldb + nc2 * 8;
            float4 w0 = *(const float4*)p2,          w1 = *(const float4*)(p2 + 4);
            float4 x0 = *(const float4*)(p2 + PSTR), x1 = *(const float4*)(p2 + 4 + PSTR);
            uint4 o2;
            o2.x = pk(w0.x + x0.x, w0.y + x0.y);
            o2.y = pk(w0.z + x0.z, w0.w + x0.w);
            o2.z = pk(w1.x + x1.x, w1.y + x1.y);
            o2.w = pk(w1.z + x1.z, w1.w + x1.w);
            STS128U(sb + nboff2, o2);
        } else if (TRB) {
            if (BN == 128) {
                CP16(sb + aoff1, Bb + (size_t)lr  * ldb + k0 + lc * 8);
                CP16(sb + aoff2, Bb + (size_t)lr2 * ldb + k0 + lc * 8);
            } else {
                CP16(sb + aoff1, Bb + (size_t)lr * ldb + k0 + lc * 8);   // lr<64 rows only
            }
        } else {
            if (BN == 128) {
                CP16(sb + nboff1, Bb + (size_t)(k0 + nk1) * ldb + nc1 * 8);
                CP16(sb + nboff2, Bb + (size_t)(k0 + nk2) * ldb + nc2 * 8);
            } else {
                CP16(sb + nboff64, Bb + (size_t)(k0 + nk64) * ldb + nc64 * 8);
            }
        }
        CP_COMMIT();
    };

    issue(0, 0);
    issue(1, 32);

    for (int t = 0; t < T; t++) {
        CP_WAIT1();
        __syncthreads();

        if (t + 2 < T) issue((t + 2) % 3, (t + 2) << 5);
        else CP_COMMIT();

        const unsigned sa = sbase + (t % 3) * STG;
        const unsigned sb = sa + 8192;

        #pragma unroll
        for (int ks = 0; ks < 2; ks++) {
            unsigned af[2][4];
            #pragma unroll
            for (int mi = 0; mi < 2; mi++) {
                unsigned addr = sa + arow_l[mi] * 64 +
                    (((ks * 2 + achk) ^ ((arow_l[mi] >> 1) & 3)) * 16);
                LDSM4(af[mi][0], af[mi][1], af[mi][2], af[mi][3], addr);
            }
            unsigned bq[NI / 2][4];
            if (TRB) {
                #pragma unroll
                for (int nj = 0; nj < NI / 2; nj++) {
                    int nl = bn_base + nj * 16;
                    unsigned addr = sb + nl * 64 +
                        (((ks * 2 + boct) ^ ((nl >> 1) & 3)) * 16);
                    LDSM4(bq[nj][0], bq[nj][1], bq[nj][2], bq[nj][3], addr);
                }
            } else {
                const int kl = ks * 16 + nn_kl;
                const unsigned sbh = (BN == 128) ? (sb + wn * 4096 + kl * 128)
                                                 : (sb + kl * 128);
                const int cbase = (BN == 128) ? 0 : wn * 4;
                #pragma unroll
                for (int nj = 0; nj < NI / 2; nj++) {
                    unsigned addr = sbh + (((cbase + nj * 2 + nn_ch) ^ (kl & 7)) * 16);
                    LDSM4T(bq[nj][0], bq[nj][1], bq[nj][2], bq[nj][3], addr);
                }
            }
            #pragma unroll
            for (int nj = 0; nj < NI / 2; nj++) {
                #pragma unroll
                for (int p = 0; p < 2; p++) {
                    unsigned b0 = bq[nj][p * 2], b1 = bq[nj][p * 2 + 1];
                    const int ni = nj * 2 + p;
                    #pragma unroll
                    for (int mi = 0; mi < 2; mi++)
                        mma_bf16(acc[mi][ni], af[mi], b0, b1);
                }
            }
        }
    }

    // ---- epilogue ----
    #pragma unroll
    for (int mi = 0; mi < 2; mi++) {
        const int r0 = row0 + wm * 32 + mi * 16 + grp;
        const int r1 = r0 + 8;
        float bv0 = 0.0f, bv1 = 0.0f;
        if (BIAS) {
            const float* bp = bias + (size_t)z * sBias;
            bv0 = bp[r0]; bv1 = bp[r1];
        }
        float s0 = 0.0f, s1 = 0.0f;
        #pragma unroll
        for (int ni = 0; ni < NI; ni++) {
            const int c = col0 + wn * (BN / 2) + ni * 8 + 2 * qd;
            if (GUARDN && c >= nvalid) continue;
            float d0 = acc[mi][ni][0] + bv0, d1 = acc[mi][ni][1] + bv0;
            float d2 = acc[mi][ni][2] + bv1, d3 = acc[mi][ni][3] + bv1;
            if (RES) {
                const float* rp = res + (size_t)z * sR;
                float2 q0 = *(const float2*)&rp[(size_t)r0 * ldc + c];
                float2 q1 = *(const float2*)&rp[(size_t)r1 * ldc + c];
                d0 += q0.x; d1 += q0.y; d2 += q1.x; d3 += q1.y;
            }
            if (DOT) {
                float w0 = bias[c], w1 = bias[c + 1];
                s0 += d0 * w0 + d1 * w1;
                s1 += d2 * w0 + d3 * w1;
            }
            if (OUTBF) {
                __nv_bfloat16* Cb = (__nv_bfloat16*)Cv + (size_t)z * sC;
                *(unsigned*)&Cb[(size_t)r0 * ldc + c] = pk(d0, d1);
                *(unsigned*)&Cb[(size_t)r1 * ldc + c] = pk(d2, d3);
            } else {
                float* Cf = (float*)Cv + (size_t)z * sC + (size_t)part * sPart;
                *(float2*)&Cf[(size_t)r0 * ldc + c] = make_float2(d0, d1);
                *(float2*)&Cf[(size_t)r1 * ldc + c] = make_float2(d2, d3);
            }
        }
        if (DOT) {
            s0 += __shfl_xor_sync(0xffffffffu, s0, 1);
            s0 += __shfl_xor_sync(0xffffffffu, s0, 2);
            s1 += __shfl_xor_sync(0xffffffffu, s1, 1);
            s1 += __shfl_xor_sync(0xffffffffu, s1, 2);
            if (qd == 0) {
                atomicAdd(&g_bias3[(size_t)z * CCH + r0], s0);
                atomicAdd(&g_bias3[(size_t)z * CCH + r1], s1);
            }
        }
    }
}

// ---------------- prep / elementwise ----------------
__global__ void f2b2(const float* __restrict__ s1, int n1,
                     const float* __restrict__ s2, int n2,
                     const float* __restrict__ b_proj) {
    int i = blockIdx.x * 256 + threadIdx.x;
    if (i < n1) g_wqkv[i] = __float2bfloat16(s1[i]);
    else if (i < n1 + n2) g_wproj[i - n1] = __float2bfloat16(s2[i - n1]);
    else if (i < n1 + n2 + BATCH * CCH) {
        int j = i - n1 - n2;
        g_bias3[j] = b_proj[j % CCH];
    }
}

__global__ __launch_bounds__(256)
void prep_xn(const float* __restrict__ x,
             const float* __restrict__ gamma, const float* __restrict__ beta,
             const float* __restrict__ mean,  const float* __restrict__ var) {
    const int b = blockIdx.y, c = blockIdx.x;
    const float s = gamma[c] * rsqrtf(var[c] + 1e-5f);
    const float h = beta[c] - mean[c] * s;
    const float* src = x + ((size_t)b * CCH + c) * HN;
    __nv_bfloat16* dst = g_xnb + ((size_t)b * CCH + c) * NPAD;
    const int tid = threadIdx.x;
    __shared__ float red[256];

    float acc = 0.0f;
    for (int i = tid; i < HN / 8; i += 256) {
        float4 v0 = *(const float4*)(src + i * 8);
        float4 v1 = *(const float4*)(src + i * 8 + 4);
        float f0 = v0.x * s + h, f1 = v0.y * s + h, f2 = v0.z * s + h, f3 = v0.w * s + h;
        float f4 = v1.x * s + h, f5 = v1.y * s + h, f6 = v1.z * s + h, f7 = v1.w * s + h;
        uint4 o;
        o.x = pk(f0, f1); o.y = pk(f2, f3); o.z = pk(f4, f5); o.w = pk(f6, f7);
        *(uint4*)(dst + i * 8) = o;
        acc += f0 + f1 + f2 + f3 + f4 + f5 + f6 + f7;
    }
    red[tid] = acc;
    __syncthreads();
    for (int st = 128; st > 0; st >>= 1) {
        if (tid < st) red[tid] += red[tid + st];
        __syncthreads();
    }
    if (tid == 0) g_s[b * CCH + c] = red[0];
}

__global__ __launch_bounds__(128)
void qk_stats(const float* __restrict__ b_qkv) {
    const int b = blockIdx.y, r = blockIdx.x;
    const __nv_bfloat16* w = g_wqkv + (size_t)r * CCH;
    const __nv_bfloat16* p = g_P + ((size_t)b * 2 * CCH + r) * CCH;
    const float* s = g_s + b * CCH;
    const int tid = threadIdx.x;
    __shared__ float r1[128], r2[128];
    float a1 = 0.0f, a2 = 0.0f;
    #pragma unroll
    for (int j = 0; j < 3; j++) {
        int e = tid + j * 128;
        float wv = __bfloat162float(w[e]);
        a1 += wv * __bfloat162float(p[e]);
        a2 += wv * s[e];
    }
    r1[tid] = a1; r2[tid] = a2;
    __syncthreads();
    for (int st = 64; st > 0; st >>= 1) {
        if (tid < st) { r1[tid] += r1[tid + st]; r2[tid] += r2[tid + st]; }
        __syncthreads();
    }
    if (tid == 0) {
        float bias = b_qkv[r];
        g_sumsq[b * 2 * CCH + r] = r1[0] + 2.0f * bias * r2[0] + (float)HN * bias * bias;
        g_tvec [b * 2 * CCH + r] = r2[0];
    }
}

__global__ __launch_bounds__(128)
void softmax_rows(const float* __restrict__ tptr, const float* __restrict__ b_qkv) {
    const int b = blockIdx.y, cc = blockIdx.x;
    const float* L = g_attn + ((size_t)b * CCH + cc) * CCH;
    __nv_bfloat16* orow = g_attnb + ((size_t)b * CCH + cc) * CCH;
    const int tid = threadIdx.x;
    __shared__ float red[128];

    const float* ssq = g_sumsq + (size_t)b * 2 * CCH;
    const float* tv  = g_tvec  + (size_t)b * 2 * CCH;
    const float bqv = b_qkv[cc];
    const float tqv = tv[cc];
    const float tsc = tptr[0] / fmaxf(sqrtf(ssq[cc]), 1e-12f);

    float v[3];
    #pragma unroll
    for (int j = 0; j < 3; j++) {
        int d = tid + j * 128;
        float bk = b_qkv[CCH + d];
        float tk = tv[CCH + d];
        float ik = 1.0f / fmaxf(sqrtf(ssq[CCH + d]), 1e-12f);
        float logit = L[d] + bqv * tk + bk * tqv + (float)HN * bqv * bk;
        v[j] = logit * tsc * ik;
    }

    float m = fmaxf(v[0], fmaxf(v[1], v[2]));
    red[tid] = m;
    __syncthreads();
    for (int st = 64; st > 0; st >>= 1) {
        if (tid < st) red[tid] = fmaxf(red[tid], red[tid + st]);
        __syncthreads();
    }
    m = red[0];
    __syncthreads();

    float e0 = expf(v[0] - m), e1 = expf(v[1] - m), e2 = expf(v[2] - m);
    red[tid] = e0 + e1 + e2;
    __syncthreads();
    for (int st = 64; st > 0; st >>= 1) {
        if (tid < st) red[tid] += red[tid + st];
        __syncthreads();
    }
    float inv = 1.0f / red[0];

    orow[tid]       = __float2bfloat16(e0 * inv);
    orow[tid + 128] = __float2bfloat16(e1 * inv);
    orow[tid + 256] = __float2bfloat16(e2 * inv);
}

// ---------------- host ----------------
extern "C" void kernel_launch(void* const* d_in, const int* in_sizes, int n_in,
                              void* d_out, int out_size)
{
    const float* x      = (const float*)d_in[0];
    const float* w_qkv  = (const float*)d_in[1];
    const float* b_qkv  = (const float*)d_in[2];
    const float* w_proj = (const float*)d_in[3];
    const float* b_proj = (const float*)d_in[4];
    const float* gamma  = (const float*)d_in[5];
    const float* beta   = (const float*)d_in[6];
    const float* mean   = (const float*)d_in[7];
    const float* var    = (const float*)d_in[8];
    const float* temp   = (const float*)d_in[9];
    float* out = (float*)d_out;

    __nv_bfloat16 *xnb, *P, *attnb, *w2, *w3, *wqkvb, *wprojb;
    float *attn, *bias3;
    cudaGetSymbolAddress((void**)&xnb,    g_xnb);
    cudaGetSymbolAddress((void**)&P,      g_P);
    cudaGetSymbolAddress((void**)&attn,   g_attn);
    cudaGetSymbolAddress((void**)&attnb,  g_attnb);
    cudaGetSymbolAddress((void**)&w2,     g_w2);
    cudaGetSymbolAddress((void**)&w3,     g_w3);
    cudaGetSymbolAddress((void**)&wqkvb,  g_wqkv);
    cudaGetSymbolAddress((void**)&wprojb, g_wproj);
    cudaGetSymbolAddress((void**)&bias3,  g_bias3);

    const long sXN  = (long)CCH * NPAD;
    const long sATT = (long)CCH * CCH;
    const long sP   = (long)2 * CCH * CCH;
    const long sOUT = (long)CCH * HN;

    // 0) prep
    f2b2<<<(3*CCH*CCH + CCH*CCH + BATCH*CCH + 255)/256, 256>>>(
        w_qkv, 3*CCH*CCH, w_proj, CCH*CCH, b_proj);
    prep_xn<<<dim3(CCH, BATCH), 256>>>(x, gamma, beta, mean, var);

    // 1) Gram partials: G = xn . xn^T (NT, K=3136, split-K=2, fp32 partials)
    bgemm<KSPL, 128, true, false, false, false, false, false, false>
        <<<dim3(CCH/128, CCH/128, BATCH*KSPL), 256>>>(
        xnb, xnb, attn, nullptr, nullptr,
        KCH, NPAD, NPAD, CCH, CCH, sXN, sXN, sATT, 0, (long)PSTR, 0);

    // 2) P = [Wq;Wk] @ G  (NN, M=768, K=384; B = bf16(p0+p1) on the fly)
    bgemm<1, 128, false, true, false, false, true, false, false>
        <<<dim3(CCH/128, 2*CCH/128, BATCH), 256>>>(
        wqkvb, (const __nv_bfloat16*)attn, P, nullptr, nullptr,
        CCH, CCH, CCH, CCH, CCH, 0, sATT, sP, 0, 0, 0);

    // 3) L0 = P_q @ Wk^T  (NT, 384^3, BN=64 -> 288 CTAs), fp32 -> g_attn
    bgemm<1, 64, true, false, false, false, false, false, false>
        <<<dim3(CCH/64, CCH/128, BATCH), 256>>>(
        P, wqkvb + (size_t)CCH*CCH, attn, nullptr, nullptr,
        CCH, CCH, CCH, CCH, CCH, sP, 0, sATT, 0, 0, 0);

    // 4) per-row norms + bias-correction vectors
    qk_stats<<<dim3(2*CCH, BATCH), 128>>>(b_qkv);

    // 5) softmax -> bf16
    softmax_rows<<<dim3(CCH, BATCH), 128>>>(temp, b_qkv);

    // 6) W2 = wproj @ attn (NN, 384^3, BN=64), bf16 + fused bias3 dot
    bgemm<1, 64, false, false, false, false, true, false, true>
        <<<dim3(CCH/64, CCH/128, BATCH), 256>>>(
        wprojb, attnb, w2, b_qkv + 2*CCH, nullptr,
        CCH, CCH, CCH, CCH, CCH, 0, sATT, sATT, 0, 0, 0);

    // 7) W3 = W2 @ Wv  (NN, 384^3, BN=64), bf16
    bgemm<1, 64, false, false, false, false, true, false, false>
        <<<dim3(CCH/64, CCH/128, BATCH), 256>>>(
        w2, wqkvb + (size_t)2*CCH*CCH, w3, nullptr, nullptr,
        CCH, CCH, CCH, CCH, CCH, sATT, 0, sATT, 0, 0, 0);

    // 8) out = W3 @ xn + bias3 + x  (NN, N=3200 guarded to 3136, fp32)
    bgemm<1, 128, false, false, true, true, false, true, false>
        <<<dim3(NPAD/128, CCH/128, BATCH), 256>>>(
        w3, xnb, out, bias3, x,
        CCH, CCH, NPAD, HN, HN, sATT, sXN, sOUT, sOUT, 0, CCH);
}